// round 1
// baseline (speedup 1.0000x reference)
#include <cuda_runtime.h>
#include <cuda_bf16.h>

#define NB    2
#define SEQ   4096
#define HID   512
#define NHEAD 8
#define HDIM  64

#define BM 128
#define BN 128
#define QT_STRIDE (BM + 4)   // 132
#define KT_STRIDE (BN + 4)   // 132
#define VS_STRIDE (HDIM + 4) // 68
#define PS_STRIDE (BM + 4)   // 132

#define SMEM_FLOATS (HDIM*QT_STRIDE + HDIM*KT_STRIDE + BN*VS_STRIDE + BN*PS_STRIDE)
// 8448 + 8448 + 8704 + 16896 = 42496 floats = 169984 bytes

#define L2E 1.44269504088896340736f

// scratch for attention output (allocation-free rule: __device__ global)
__device__ float g_ctx[NB * SEQ * HID];

// ---------------------------------------------------------------------------
// Fused flash attention with volatility (distance^2) penalty.
// Grid: (SEQ/BM, NB*NHEAD). 256 threads (16x16), 8x8 score micro-tile,
// 8x4 output micro-tile. Online softmax in exp2 domain.
// ---------------------------------------------------------------------------
__global__ void __launch_bounds__(256, 1)
attn_kernel(const float* __restrict__ Q, const float* __restrict__ K,
            const float* __restrict__ V, const float* __restrict__ sigma,
            const float* __restrict__ lam_p)
{
    extern __shared__ float sm[];
    float* Qt = sm;                          // [HDIM][BM+4]  Q transposed, pre-scaled
    float* Kt = Qt + HDIM * QT_STRIDE;       // [HDIM][BN+4]  K transposed
    float* Vs = Kt + HDIM * KT_STRIDE;       // [BN][HDIM+4]  V row-major
    float* Ps = Vs + BN * VS_STRIDE;         // [BN][BM+4]    P transposed (n-major)

    const int bb = blockIdx.y >> 3;   // batch
    const int hh = blockIdx.y & 7;    // head
    const int qbase = blockIdx.x * BM;
    const int tid = threadIdx.x;
    const int tx = tid & 15;
    const int ty = tid >> 4;

    // risk constant: penalty(i,j) = riskC * (i-j)^2
    float sc = fminf(fmaxf(sigma[bb], 0.001f), 0.2f);
    float sn = (sc - 0.001f) * (1.0f / 0.199f);
    const float riskC = lam_p[0] * 0.1f * sn * (1.0f / ((float)SEQ * (float)SEQ));

    const float* Qb = Q + (size_t)bb * SEQ * HID + hh * HDIM;
    const float* Kb = K + (size_t)bb * SEQ * HID + hh * HDIM;
    const float* Vb = V + (size_t)bb * SEQ * HID + hh * HDIM;

    // ---- load Q tile, transposed into Qt[d][m], pre-scaled by 1/sqrt(hd)=0.125
    {
        const int r  = tid >> 1;           // 0..127
        const int c0 = (tid & 1) << 5;     // 0 or 32
        const float4* src = (const float4*)(Qb + (size_t)(qbase + r) * HID + c0);
        #pragma unroll
        for (int i = 0; i < 8; i++) {
            float4 v = src[i];
            int c = c0 + i * 4;
            Qt[(c + 0) * QT_STRIDE + r] = v.x * 0.125f;
            Qt[(c + 1) * QT_STRIDE + r] = v.y * 0.125f;
            Qt[(c + 2) * QT_STRIDE + r] = v.z * 0.125f;
            Qt[(c + 3) * QT_STRIDE + r] = v.w * 0.125f;
        }
    }

    float m_i[8], l_i[8], acc[8][4];
    #pragma unroll
    for (int i = 0; i < 8; i++) {
        m_i[i] = -1e30f;
        l_i[i] = 0.0f;
        #pragma unroll
        for (int d = 0; d < 4; d++) acc[i][d] = 0.0f;
    }

    const int qrow0 = qbase + ty * 8;

    for (int kt = 0; kt < SEQ / BN; kt++) {
        const int kbase = kt * BN;

        __syncthreads();  // previous iteration's Kt/Vs/Ps readers must finish

        // ---- load K (transposed) and V (row-major) tiles
        {
            const int r  = tid >> 1;
            const int c0 = (tid & 1) << 5;
            const float4* ks = (const float4*)(Kb + (size_t)(kbase + r) * HID + c0);
            const float4* vs = (const float4*)(Vb + (size_t)(kbase + r) * HID + c0);
            #pragma unroll
            for (int i = 0; i < 8; i++) {
                float4 kv = ks[i];
                int c = c0 + i * 4;
                Kt[(c + 0) * KT_STRIDE + r] = kv.x;
                Kt[(c + 1) * KT_STRIDE + r] = kv.y;
                Kt[(c + 2) * KT_STRIDE + r] = kv.z;
                Kt[(c + 3) * KT_STRIDE + r] = kv.w;
                float4 vv = vs[i];
                *(float4*)&Vs[r * VS_STRIDE + c] = vv;
            }
        }
        __syncthreads();

        // ---- scores: S = (Q*scale) @ K^T  (8x8 per thread)
        float s[8][8];
        #pragma unroll
        for (int i = 0; i < 8; i++)
            #pragma unroll
            for (int j = 0; j < 8; j++) s[i][j] = 0.0f;

        #pragma unroll 8
        for (int d = 0; d < HDIM; d++) {
            float4 q0 = *(const float4*)&Qt[d * QT_STRIDE + ty * 8];
            float4 q1 = *(const float4*)&Qt[d * QT_STRIDE + ty * 8 + 4];
            float4 k0 = *(const float4*)&Kt[d * KT_STRIDE + tx * 8];
            float4 k1 = *(const float4*)&Kt[d * KT_STRIDE + tx * 8 + 4];
            float qf[8] = {q0.x, q0.y, q0.z, q0.w, q1.x, q1.y, q1.z, q1.w};
            float kf[8] = {k0.x, k0.y, k0.z, k0.w, k1.x, k1.y, k1.z, k1.w};
            #pragma unroll
            for (int i = 0; i < 8; i++)
                #pragma unroll
                for (int j = 0; j < 8; j++)
                    s[i][j] = fmaf(qf[i], kf[j], s[i][j]);
        }

        // ---- risk penalty + online softmax (per query row)
        const int kcol0 = kbase + tx * 8;
        #pragma unroll
        for (int i = 0; i < 8; i++) {
            const float qi = (float)(qrow0 + i);
            float rm = -1e30f;
            #pragma unroll
            for (int j = 0; j < 8; j++) {
                float diff = qi - (float)(kcol0 + j);
                s[i][j] = fmaf(-riskC * diff, diff, s[i][j]);
                rm = fmaxf(rm, s[i][j]);
            }
            // reduce max across the 16 tx lanes (xor<16 stays in-group)
            #pragma unroll
            for (int msk = 1; msk < 16; msk <<= 1)
                rm = fmaxf(rm, __shfl_xor_sync(0xffffffffu, rm, msk));

            float mnew  = fmaxf(m_i[i], rm);
            float alpha = exp2f((m_i[i] - mnew) * L2E);
            m_i[i] = mnew;

            float lsum = 0.0f;
            #pragma unroll
            for (int j = 0; j < 8; j++) {
                float p = exp2f((s[i][j] - mnew) * L2E);
                s[i][j] = p;
                lsum += p;
            }
            #pragma unroll
            for (int msk = 1; msk < 16; msk <<= 1)
                lsum += __shfl_xor_sync(0xffffffffu, lsum, msk);

            l_i[i] = l_i[i] * alpha + lsum;
            #pragma unroll
            for (int d = 0; d < 4; d++) acc[i][d] *= alpha;
        }

        // ---- stage P transposed: Ps[n][m] (float4 along m to soften conflicts)
        #pragma unroll
        for (int j = 0; j < 8; j++) {
            float4 v0 = make_float4(s[0][j], s[1][j], s[2][j], s[3][j]);
            float4 v1 = make_float4(s[4][j], s[5][j], s[6][j], s[7][j]);
            float* dst = &Ps[(tx * 8 + j) * PS_STRIDE + ty * 8];
            *(float4*)dst       = v0;
            *(float4*)(dst + 4) = v1;
        }
        __syncthreads();

        // ---- acc += P @ V  (8 rows x 4 d-cols per thread)
        #pragma unroll 4
        for (int n = 0; n < BN; n++) {
            float4 a0 = *(const float4*)&Ps[n * PS_STRIDE + ty * 8];
            float4 a1 = *(const float4*)&Ps[n * PS_STRIDE + ty * 8 + 4];
            float4 bv = *(const float4*)&Vs[n * VS_STRIDE + tx * 4];
            float af[8] = {a0.x, a0.y, a0.z, a0.w, a1.x, a1.y, a1.z, a1.w};
            float bf[4] = {bv.x, bv.y, bv.z, bv.w};
            #pragma unroll
            for (int i = 0; i < 8; i++)
                #pragma unroll
                for (int d = 0; d < 4; d++)
                    acc[i][d] = fmaf(af[i], bf[d], acc[i][d]);
        }
    }

    // ---- epilogue: ctx = acc / l
    float* ctxb = g_ctx + (size_t)bb * SEQ * HID + hh * HDIM;
    #pragma unroll
    for (int i = 0; i < 8; i++) {
        float inv = 1.0f / l_i[i];
        float4 o = make_float4(acc[i][0] * inv, acc[i][1] * inv,
                               acc[i][2] * inv, acc[i][3] * inv);
        *(float4*)&ctxb[(size_t)(qrow0 + i) * HID + tx * 4] = o;
    }
}

// ---------------------------------------------------------------------------
// out = ctx @ W^T + b   (M=8192, N=512, K=512) — 128x128 tile, 8x8 micro
// ---------------------------------------------------------------------------
__global__ void __launch_bounds__(256, 2)
proj_kernel(const float* __restrict__ W, const float* __restrict__ bias,
            float* __restrict__ out)
{
    __shared__ __align__(16) float As[16][132];  // [k][m]
    __shared__ __align__(16) float Bs[16][132];  // [k][n]

    const int mbase = blockIdx.x * 128;
    const int nbase = blockIdx.y * 128;
    const int tid = threadIdx.x;
    const int tx = tid & 15;
    const int ty = tid >> 4;

    float acc[8][8];
    #pragma unroll
    for (int i = 0; i < 8; i++)
        #pragma unroll
        for (int j = 0; j < 8; j++) acc[i][j] = 0.0f;

    for (int kt = 0; kt < HID / 16; kt++) {
        const int k0 = kt * 16;
        __syncthreads();
        #pragma unroll
        for (int u = 0; u < 2; u++) {
            int f  = u * 256 + tid;
            int r  = f >> 2;          // 0..127
            int cf = (f & 3) * 4;     // 0,4,8,12
            float4 a = *(const float4*)&g_ctx[(size_t)(mbase + r) * HID + k0 + cf];
            As[cf + 0][r] = a.x; As[cf + 1][r] = a.y;
            As[cf + 2][r] = a.z; As[cf + 3][r] = a.w;
            float4 w = *(const float4*)&W[(size_t)(nbase + r) * HID + k0 + cf];
            Bs[cf + 0][r] = w.x; Bs[cf + 1][r] = w.y;
            Bs[cf + 2][r] = w.z; Bs[cf + 3][r] = w.w;
        }
        __syncthreads();

        #pragma unroll
        for (int k = 0; k < 16; k++) {
            float4 a0 = *(const float4*)&As[k][ty * 8];
            float4 a1 = *(const float4*)&As[k][ty * 8 + 4];
            float4 b0 = *(const float4*)&Bs[k][tx * 8];
            float4 b1 = *(const float4*)&Bs[k][tx * 8 + 4];
            float af[8] = {a0.x, a0.y, a0.z, a0.w, a1.x, a1.y, a1.z, a1.w};
            float bf[8] = {b0.x, b0.y, b0.z, b0.w, b1.x, b1.y, b1.z, b1.w};
            #pragma unroll
            for (int i = 0; i < 8; i++)
                #pragma unroll
                for (int j = 0; j < 8; j++)
                    acc[i][j] = fmaf(af[i], bf[j], acc[i][j]);
        }
    }

    const int n0 = nbase + tx * 8;
    float4 b0 = *(const float4*)&bias[n0];
    float4 b1 = *(const float4*)&bias[n0 + 4];
    #pragma unroll
    for (int i = 0; i < 8; i++) {
        int m = mbase + ty * 8 + i;
        float4 o0 = make_float4(acc[i][0] + b0.x, acc[i][1] + b0.y,
                                acc[i][2] + b0.z, acc[i][3] + b0.w);
        float4 o1 = make_float4(acc[i][4] + b1.x, acc[i][5] + b1.y,
                                acc[i][6] + b1.z, acc[i][7] + b1.w);
        *(float4*)&out[(size_t)m * HID + n0]     = o0;
        *(float4*)&out[(size_t)m * HID + n0 + 4] = o1;
    }
}

extern "C" void kernel_launch(void* const* d_in, const int* in_sizes, int n_in,
                              void* d_out, int out_size)
{
    const float* Q     = (const float*)d_in[0];
    const float* K     = (const float*)d_in[1];
    const float* V     = (const float*)d_in[2];
    const float* sigma = (const float*)d_in[3];
    const float* lam   = (const float*)d_in[4];
    const float* W     = (const float*)d_in[5];
    const float* bias  = (const float*)d_in[6];
    float* out = (float*)d_out;

    cudaFuncSetAttribute(attn_kernel, cudaFuncAttributeMaxDynamicSharedMemorySize,
                         SMEM_FLOATS * (int)sizeof(float));

    dim3 g1(SEQ / BM, NB * NHEAD);
    attn_kernel<<<g1, 256, SMEM_FLOATS * sizeof(float)>>>(Q, K, V, sigma, lam);

    dim3 g2(NB * SEQ / 128, HID / 128);
    proj_kernel<<<g2, 256>>>(W, bias, out);
}

// round 2
// speedup vs baseline: 1.0820x; 1.0820x over previous
#include <cuda_runtime.h>
#include <cuda_bf16.h>

#define NB    2
#define SEQ   4096
#define HID   512
#define NHEAD 8
#define HDIM  64

#define BM 128
#define BN 128
#define QT_STRIDE (BM + 4)   // 132
#define KT_STRIDE (BN + 4)   // 132
#define VS_STRIDE (HDIM + 4) // 68
#define PS_STRIDE (BM + 4)   // 132

#define SMEM_FLOATS (HDIM*QT_STRIDE + HDIM*KT_STRIDE + BN*VS_STRIDE + BN*PS_STRIDE)

#define L2E 1.44269504088896340736f

typedef unsigned long long u64;

__device__ __forceinline__ u64 pack2(float lo, float hi) {
    u64 r; asm("mov.b64 %0, {%1, %2};" : "=l"(r) : "f"(lo), "f"(hi)); return r;
}
__device__ __forceinline__ void unpack2(u64 v, float& lo, float& hi) {
    asm("mov.b64 {%0, %1}, %2;" : "=f"(lo), "=f"(hi) : "l"(v));
}
__device__ __forceinline__ void fma2(u64& d, u64 a, u64 b) {
    asm("fma.rn.f32x2 %0, %1, %2, %0;" : "+l"(d) : "l"(a), "l"(b));
}
__device__ __forceinline__ void mul2(u64& d, u64 a) {
    asm("mul.rn.f32x2 %0, %0, %1;" : "+l"(d) : "l"(a));
}

// scratch for attention output (allocation-free rule: __device__ global)
__device__ float g_ctx[NB * SEQ * HID];

// ---------------------------------------------------------------------------
// Fused flash attention with volatility (distance^2) penalty.
// Grid: (SEQ/BM, NB*NHEAD). 256 threads (16x16). Score micro-tile 8x8,
// packed f32x2 along the row (i) axis. Online softmax in exp2 domain.
// ---------------------------------------------------------------------------
__global__ void __launch_bounds__(256, 1)
attn_kernel(const float* __restrict__ Q, const float* __restrict__ K,
            const float* __restrict__ V, const float* __restrict__ sigma,
            const float* __restrict__ lam_p)
{
    extern __shared__ float sm[];
    float* Qt = sm;                          // [HDIM][BM+4]  Q^T, pre-scaled
    float* Kt = Qt + HDIM * QT_STRIDE;       // [HDIM][BN+4]  K^T
    float* Vs = Kt + HDIM * KT_STRIDE;       // [BN][HDIM+4]  V row-major
    float* Ps = Vs + BN * VS_STRIDE;         // [BN][BM+4]    P^T (n-major)

    const int bb = blockIdx.y >> 3;
    const int hh = blockIdx.y & 7;
    const int qbase = blockIdx.x * BM;
    const int tid = threadIdx.x;
    const int tx = tid & 15;
    const int ty = tid >> 4;

    float sc = fminf(fmaxf(sigma[bb], 0.001f), 0.2f);
    float sn = (sc - 0.001f) * (1.0f / 0.199f);
    const float riskC = lam_p[0] * 0.1f * sn * (1.0f / ((float)SEQ * (float)SEQ));

    const float* Qb = Q + (size_t)bb * SEQ * HID + hh * HDIM;
    const float* Kb = K + (size_t)bb * SEQ * HID + hh * HDIM;
    const float* Vb = V + (size_t)bb * SEQ * HID + hh * HDIM;

    // ---- load Q tile transposed, pre-scaled by 1/sqrt(hd) = 0.125
    {
        const int r  = tid >> 1;
        const int c0 = (tid & 1) << 5;
        const float4* src = (const float4*)(Qb + (size_t)(qbase + r) * HID + c0);
        #pragma unroll
        for (int i = 0; i < 8; i++) {
            float4 v = src[i];
            int c = c0 + i * 4;
            Qt[(c + 0) * QT_STRIDE + r] = v.x * 0.125f;
            Qt[(c + 1) * QT_STRIDE + r] = v.y * 0.125f;
            Qt[(c + 2) * QT_STRIDE + r] = v.z * 0.125f;
            Qt[(c + 3) * QT_STRIDE + r] = v.w * 0.125f;
        }
    }

    // row-pair state: rows (2*i2, 2*i2+1)
    float m_e[4], m_o[4], l_e[4], l_o[4];
    u64 acc2[4][4];   // [i2][d]  packed pairs of rows
    #pragma unroll
    for (int i2 = 0; i2 < 4; i2++) {
        m_e[i2] = -1e30f; m_o[i2] = -1e30f;
        l_e[i2] = 0.0f;   l_o[i2] = 0.0f;
        #pragma unroll
        for (int d = 0; d < 4; d++) acc2[i2][d] = 0ull;
    }

    const int qrow0 = qbase + ty * 8;

    for (int kt = 0; kt < SEQ / BN; kt++) {
        const int kbase = kt * BN;

        __syncthreads();

        // ---- load K (transposed) and V (row-major) tiles
        {
            const int r  = tid >> 1;
            const int c0 = (tid & 1) << 5;
            const float4* ks = (const float4*)(Kb + (size_t)(kbase + r) * HID + c0);
            const float4* vs = (const float4*)(Vb + (size_t)(kbase + r) * HID + c0);
            #pragma unroll
            for (int i = 0; i < 8; i++) {
                float4 kv = ks[i];
                int c = c0 + i * 4;
                Kt[(c + 0) * KT_STRIDE + r] = kv.x;
                Kt[(c + 1) * KT_STRIDE + r] = kv.y;
                Kt[(c + 2) * KT_STRIDE + r] = kv.z;
                Kt[(c + 3) * KT_STRIDE + r] = kv.w;
                float4 vv = vs[i];
                *(float4*)&Vs[r * VS_STRIDE + c] = vv;
            }
        }
        __syncthreads();

        // ---- scores: S = (Q*scale) @ K^T, packed along i
        u64 s2[4][8];
        #pragma unroll
        for (int i2 = 0; i2 < 4; i2++)
            #pragma unroll
            for (int j = 0; j < 8; j++) s2[i2][j] = 0ull;

        #pragma unroll 4
        for (int d = 0; d < HDIM; d++) {
            const ulonglong2* qp = (const ulonglong2*)&Qt[d * QT_STRIDE + ty * 8];
            ulonglong2 qa = qp[0], qb2 = qp[1];
            u64 q2[4] = {qa.x, qa.y, qb2.x, qb2.y};
            float4 k0 = *(const float4*)&Kt[d * KT_STRIDE + tx * 8];
            float4 k1 = *(const float4*)&Kt[d * KT_STRIDE + tx * 8 + 4];
            float kf[8] = {k0.x, k0.y, k0.z, k0.w, k1.x, k1.y, k1.z, k1.w};
            #pragma unroll
            for (int j = 0; j < 8; j++) {
                u64 kd = pack2(kf[j], kf[j]);
                #pragma unroll
                for (int i2 = 0; i2 < 4; i2++)
                    fma2(s2[i2][j], q2[i2], kd);
            }
        }

        // ---- risk penalty + online softmax (two rows per i2)
        const int kcol0 = kbase + tx * 8;
        #pragma unroll
        for (int i2 = 0; i2 < 4; i2++) {
            float r0[8], r1[8];
            #pragma unroll
            for (int j = 0; j < 8; j++) unpack2(s2[i2][j], r0[j], r1[j]);

            const float qi0 = (float)(qrow0 + 2 * i2);
            const float qi1 = qi0 + 1.0f;
            float rm0 = -1e30f, rm1 = -1e30f;
            #pragma unroll
            for (int j = 0; j < 8; j++) {
                float cj = (float)(kcol0 + j);
                float d0 = qi0 - cj;
                r0[j] = fmaf(-riskC * d0, d0, r0[j]);
                rm0 = fmaxf(rm0, r0[j]);
                float d1 = qi1 - cj;
                r1[j] = fmaf(-riskC * d1, d1, r1[j]);
                rm1 = fmaxf(rm1, r1[j]);
            }
            #pragma unroll
            for (int msk = 1; msk < 16; msk <<= 1) {
                rm0 = fmaxf(rm0, __shfl_xor_sync(0xffffffffu, rm0, msk));
                rm1 = fmaxf(rm1, __shfl_xor_sync(0xffffffffu, rm1, msk));
            }

            float mn0 = fmaxf(m_e[i2], rm0);
            float mn1 = fmaxf(m_o[i2], rm1);
            float a0 = exp2f((m_e[i2] - mn0) * L2E);
            float a1 = exp2f((m_o[i2] - mn1) * L2E);
            m_e[i2] = mn0; m_o[i2] = mn1;

            float ls0 = 0.0f, ls1 = 0.0f;
            #pragma unroll
            for (int j = 0; j < 8; j++) {
                r0[j] = exp2f((r0[j] - mn0) * L2E); ls0 += r0[j];
                r1[j] = exp2f((r1[j] - mn1) * L2E); ls1 += r1[j];
            }
            #pragma unroll
            for (int msk = 1; msk < 16; msk <<= 1) {
                ls0 += __shfl_xor_sync(0xffffffffu, ls0, msk);
                ls1 += __shfl_xor_sync(0xffffffffu, ls1, msk);
            }
            l_e[i2] = l_e[i2] * a0 + ls0;
            l_o[i2] = l_o[i2] * a1 + ls1;

            u64 al2 = pack2(a0, a1);
            #pragma unroll
            for (int d = 0; d < 4; d++) mul2(acc2[i2][d], al2);

            #pragma unroll
            for (int j = 0; j < 8; j++) s2[i2][j] = pack2(r0[j], r1[j]);
        }

        // ---- stage P transposed: Ps[n][m], pairs stay packed
        #pragma unroll
        for (int j = 0; j < 8; j++) {
            float* dst = &Ps[(tx * 8 + j) * PS_STRIDE + ty * 8];
            ((ulonglong2*)dst)[0] = make_ulonglong2(s2[0][j], s2[1][j]);
            ((ulonglong2*)dst)[1] = make_ulonglong2(s2[2][j], s2[3][j]);
        }
        __syncthreads();

        // ---- acc += P @ V, packed along i
        #pragma unroll 4
        for (int n = 0; n < BN; n++) {
            const ulonglong2* ap = (const ulonglong2*)&Ps[n * PS_STRIDE + ty * 8];
            ulonglong2 aa = ap[0], ab = ap[1];
            u64 a2[4] = {aa.x, aa.y, ab.x, ab.y};
            float4 bv = *(const float4*)&Vs[n * VS_STRIDE + tx * 4];
            float bf[4] = {bv.x, bv.y, bv.z, bv.w};
            #pragma unroll
            for (int d = 0; d < 4; d++) {
                u64 bd = pack2(bf[d], bf[d]);
                #pragma unroll
                for (int i2 = 0; i2 < 4; i2++)
                    fma2(acc2[i2][d], a2[i2], bd);
            }
        }
    }

    // ---- epilogue: ctx = acc / l
    float* ctxb = g_ctx + (size_t)bb * SEQ * HID + hh * HDIM;
    #pragma unroll
    for (int i2 = 0; i2 < 4; i2++) {
        float inv0 = 1.0f / l_e[i2];
        float inv1 = 1.0f / l_o[i2];
        float o0[4], o1[4];
        #pragma unroll
        for (int d = 0; d < 4; d++) unpack2(acc2[i2][d], o0[d], o1[d]);
        int row0 = qrow0 + 2 * i2;
        float4 w0 = make_float4(o0[0] * inv0, o0[1] * inv0, o0[2] * inv0, o0[3] * inv0);
        float4 w1 = make_float4(o1[0] * inv1, o1[1] * inv1, o1[2] * inv1, o1[3] * inv1);
        *(float4*)&ctxb[(size_t)row0 * HID + tx * 4]       = w0;
        *(float4*)&ctxb[(size_t)(row0 + 1) * HID + tx * 4] = w1;
    }
}

// ---------------------------------------------------------------------------
// out = ctx @ W^T + b   (M=8192, N=512, K=512) — 128x128 tile, packed f32x2
// ---------------------------------------------------------------------------
__global__ void __launch_bounds__(256, 2)
proj_kernel(const float* __restrict__ W, const float* __restrict__ bias,
            float* __restrict__ out)
{
    __shared__ __align__(16) float As[16][132];  // [k][m]
    __shared__ __align__(16) float Bs[16][132];  // [k][n]

    const int mbase = blockIdx.x * 128;
    const int nbase = blockIdx.y * 128;
    const int tid = threadIdx.x;
    const int tx = tid & 15;
    const int ty = tid >> 4;

    u64 acc2[4][8];   // [i2 (m-pairs)][j]
    #pragma unroll
    for (int i2 = 0; i2 < 4; i2++)
        #pragma unroll
        for (int j = 0; j < 8; j++) acc2[i2][j] = 0ull;

    for (int kt = 0; kt < HID / 16; kt++) {
        const int k0 = kt * 16;
        __syncthreads();
        #pragma unroll
        for (int u = 0; u < 2; u++) {
            int f  = u * 256 + tid;
            int r  = f >> 2;
            int cf = (f & 3) * 4;
            float4 a = *(const float4*)&g_ctx[(size_t)(mbase + r) * HID + k0 + cf];
            As[cf + 0][r] = a.x; As[cf + 1][r] = a.y;
            As[cf + 2][r] = a.z; As[cf + 3][r] = a.w;
            float4 w = *(const float4*)&W[(size_t)(nbase + r) * HID + k0 + cf];
            Bs[cf + 0][r] = w.x; Bs[cf + 1][r] = w.y;
            Bs[cf + 2][r] = w.z; Bs[cf + 3][r] = w.w;
        }
        __syncthreads();

        #pragma unroll
        for (int k = 0; k < 16; k++) {
            const ulonglong2* apx = (const ulonglong2*)&As[k][ty * 8];
            ulonglong2 aa = apx[0], ab = apx[1];
            u64 a2[4] = {aa.x, aa.y, ab.x, ab.y};
            float4 b0 = *(const float4*)&Bs[k][tx * 8];
            float4 b1 = *(const float4*)&Bs[k][tx * 8 + 4];
            float bf[8] = {b0.x, b0.y, b0.z, b0.w, b1.x, b1.y, b1.z, b1.w};
            #pragma unroll
            for (int j = 0; j < 8; j++) {
                u64 bd = pack2(bf[j], bf[j]);
                #pragma unroll
                for (int i2 = 0; i2 < 4; i2++)
                    fma2(acc2[i2][j], a2[i2], bd);
            }
        }
    }

    const int n0 = nbase + tx * 8;
    float4 b0 = *(const float4*)&bias[n0];
    float4 b1 = *(const float4*)&bias[n0 + 4];
    float bf[8] = {b0.x, b0.y, b0.z, b0.w, b1.x, b1.y, b1.z, b1.w};
    #pragma unroll
    for (int i2 = 0; i2 < 4; i2++) {
        float r0[8], r1[8];
        #pragma unroll
        for (int j = 0; j < 8; j++) {
            unpack2(acc2[i2][j], r0[j], r1[j]);
            r0[j] += bf[j];
            r1[j] += bf[j];
        }
        int m0 = mbase + ty * 8 + 2 * i2;
        *(float4*)&out[(size_t)m0 * HID + n0]           = make_float4(r0[0], r0[1], r0[2], r0[3]);
        *(float4*)&out[(size_t)m0 * HID + n0 + 4]       = make_float4(r0[4], r0[5], r0[6], r0[7]);
        *(float4*)&out[(size_t)(m0 + 1) * HID + n0]     = make_float4(r1[0], r1[1], r1[2], r1[3]);
        *(float4*)&out[(size_t)(m0 + 1) * HID + n0 + 4] = make_float4(r1[4], r1[5], r1[6], r1[7]);
    }
}

extern "C" void kernel_launch(void* const* d_in, const int* in_sizes, int n_in,
                              void* d_out, int out_size)
{
    const float* Q     = (const float*)d_in[0];
    const float* K     = (const float*)d_in[1];
    const float* V     = (const float*)d_in[2];
    const float* sigma = (const float*)d_in[3];
    const float* lam   = (const float*)d_in[4];
    const float* W     = (const float*)d_in[5];
    const float* bias  = (const float*)d_in[6];
    float* out = (float*)d_out;

    cudaFuncSetAttribute(attn_kernel, cudaFuncAttributeMaxDynamicSharedMemorySize,
                         SMEM_FLOATS * (int)sizeof(float));

    dim3 g1(SEQ / BM, NB * NHEAD);
    attn_kernel<<<g1, 256, SMEM_FLOATS * sizeof(float)>>>(Q, K, V, sigma, lam);

    dim3 g2(NB * SEQ / 128, HID / 128);
    proj_kernel<<<g2, 256>>>(W, bias, out);
}

// round 4
// speedup vs baseline: 2.3191x; 2.1434x over previous
#include <cuda_runtime.h>
#include <cuda_bf16.h>
#include <cstdint>

#define NB    2
#define SEQ   4096
#define HID   512
#define NHEAD 8
#define HDIM  64
#define BM    128
#define BN    64
#define NITER (SEQ / BN)
#define L2E   1.44269504088896340736f

typedef unsigned int u32;

// split pair (a,b) -> bf16x2 hi word (a in low half) + bf16x2 residual word
__device__ __forceinline__ void split2(float a, float b, u32& hw, u32& lw) {
    __nv_bfloat16 ha = __float2bfloat16(a), hb = __float2bfloat16(b);
    float ra = a - __bfloat162float(ha);
    float rb = b - __bfloat162float(hb);
    __nv_bfloat162 hv; hv.x = ha; hv.y = hb;
    __nv_bfloat162 lv; lv.x = __float2bfloat16(ra); lv.y = __float2bfloat16(rb);
    hw = *(u32*)&hv; lw = *(u32*)&lv;
}

__device__ __forceinline__ float ex2f(float x) {
    float y; asm("ex2.approx.ftz.f32 %0, %1;" : "=f"(y) : "f"(x)); return y;
}

// D += A @ B  (m16n8k16, bf16 in, fp32 acc)
__device__ __forceinline__ void mma16816(float* c, const u32* a, u32 b0, u32 b1) {
    asm volatile(
        "mma.sync.aligned.m16n8k16.row.col.f32.bf16.bf16.f32 "
        "{%0,%1,%2,%3}, {%4,%5,%6,%7}, {%8,%9}, {%0,%1,%2,%3};"
        : "+f"(c[0]), "+f"(c[1]), "+f"(c[2]), "+f"(c[3])
        : "r"(a[0]), "r"(a[1]), "r"(a[2]), "r"(a[3]), "r"(b0), "r"(b1));
}

__device__ float g_ctx[NB * SEQ * HID];

#define KSTR 72   // bf16 elems per row (144B): frag LDS conflict-free

// ---------------------------------------------------------------------------
// Flash attention, 3-pass split-bf16 HMMA, no-max softmax (shift-invariant).
// Grid (SEQ/BM, NB*NHEAD), 256 thr. Warp w owns q-rows [w*16, w*16+16).
// ---------------------------------------------------------------------------
__global__ void __launch_bounds__(256, 1)
attn_kernel(const float* __restrict__ Q, const float* __restrict__ K,
            const float* __restrict__ V, const float* __restrict__ sigma,
            const float* __restrict__ lam_p)
{
    __shared__ __align__(16) __nv_bfloat16 sKhi[BN][KSTR];     // [token][d]
    __shared__ __align__(16) __nv_bfloat16 sKlo[BN][KSTR];
    __shared__ __align__(16) __nv_bfloat16 sVhi[HDIM][KSTR];   // [d][token]
    __shared__ __align__(16) __nv_bfloat16 sVlo[HDIM][KSTR];

    const int tid  = threadIdx.x;
    const int warp = tid >> 5;
    const int lane = tid & 31;
    const int r    = lane >> 2;   // fragment row group
    const int c    = lane & 3;    // fragment col group

    const int bb = blockIdx.y >> 3;
    const int hh = blockIdx.y & 7;
    const int qbase = blockIdx.x * BM;

    float sc = fminf(fmaxf(sigma[bb], 0.001f), 0.2f);
    float sn = (sc - 0.001f) * (1.0f / 0.199f);
    const float rC = lam_p[0] * 0.1f * sn * (1.0f / ((float)SEQ * (float)SEQ)) * L2E;

    const float* Qb = Q + (size_t)bb * SEQ * HID + hh * HDIM;
    const float* Kb = K + (size_t)bb * SEQ * HID + hh * HDIM;
    const float* Vb = V + (size_t)bb * SEQ * HID + hh * HDIM;

    // ---- Q fragments (persistent): 4 k-chunks x {a0,a1,a2,a3}, hi + lo
    u32 qhi[16], qlo[16];
    {
        const float s = 0.125f * L2E;   // 1/sqrt(64) * log2(e), absorbed into Q
        const int row0 = qbase + warp * 16 + r;
        const float* q0 = Qb + (size_t)row0 * HID;
        const float* q1 = q0 + 8 * HID;
        #pragma unroll
        for (int kc = 0; kc < 4; kc++) {
            int d = kc * 16 + 2 * c;
            split2(q0[d] * s,     q0[d + 1] * s, qhi[kc * 4 + 0], qlo[kc * 4 + 0]);
            split2(q1[d] * s,     q1[d + 1] * s, qhi[kc * 4 + 1], qlo[kc * 4 + 1]);
            split2(q0[d + 8] * s, q0[d + 9] * s, qhi[kc * 4 + 2], qlo[kc * 4 + 2]);
            split2(q1[d + 8] * s, q1[d + 9] * s, qhi[kc * 4 + 3], qlo[kc * 4 + 3]);
        }
    }

    float oacc[8][4];
    #pragma unroll
    for (int i = 0; i < 8; i++)
        #pragma unroll
        for (int j = 0; j < 4; j++) oacc[i][j] = 0.0f;
    float l0 = 0.0f, l1 = 0.0f;

    const float fi0 = (float)(qbase + warp * 16 + r);
    const float fi1 = fi0 + 8.0f;

    for (int kt = 0; kt < NITER; kt++) {
        const int kbase = kt * BN;
        __syncthreads();   // previous tile's fragment reads done

        // ---- stage K tile [64 tok x 64 d] -> bf16 hi/lo, token-major
        {
            const int tok  = tid >> 2;
            const int part = tid & 3;
            const float* kr = Kb + (size_t)(kbase + tok) * HID + part * 16;
            #pragma unroll
            for (int i = 0; i < 4; i++) {
                float4 v = ((const float4*)kr)[i];
                int d = part * 16 + i * 4;
                u32 hw, lw;
                split2(v.x, v.y, hw, lw);
                *(u32*)&sKhi[tok][d]     = hw;  *(u32*)&sKlo[tok][d]     = lw;
                split2(v.z, v.w, hw, lw);
                *(u32*)&sKhi[tok][d + 2] = hw;  *(u32*)&sKlo[tok][d + 2] = lw;
            }
        }
        // ---- stage V^T tile [64 d x 64 tok] (token pairs packed in u32)
        {
            const int p  = tid & 31;          // token pair
            const int d0 = (tid >> 5) * 8;    // 8 d's per thread
            const float* v0 = Vb + (size_t)(kbase + 2 * p) * HID + d0;
            const float* v1 = v0 + HID;
            #pragma unroll
            for (int i = 0; i < 2; i++) {
                float4 a = ((const float4*)v0)[i];
                float4 b = ((const float4*)v1)[i];
                float av[4] = {a.x, a.y, a.z, a.w};
                float bv[4] = {b.x, b.y, b.z, b.w};
                #pragma unroll
                for (int k2 = 0; k2 < 4; k2++) {
                    int d = d0 + i * 4 + k2;
                    u32 hw, lw;
                    split2(av[k2], bv[k2], hw, lw);
                    *(u32*)&sVhi[d][2 * p] = hw;
                    *(u32*)&sVlo[d][2 * p] = lw;
                }
            }
        }
        __syncthreads();

        // ---- S = Qhi*Khi + Qlo*Khi + Qhi*Klo   (16 x 64 per warp)
        float sacc[8][4];
        #pragma unroll
        for (int i = 0; i < 8; i++)
            #pragma unroll
            for (int j = 0; j < 4; j++) sacc[i][j] = 0.0f;

        #pragma unroll
        for (int kc = 0; kc < 4; kc++) {
            const int kk = kc * 16 + 2 * c;
            #pragma unroll
            for (int nt = 0; nt < 8; nt++) {
                const int n = nt * 8 + r;
                u32 b0 = *(const u32*)&sKhi[n][kk];
                u32 b1 = *(const u32*)&sKhi[n][kk + 8];
                mma16816(sacc[nt], &qhi[kc * 4], b0, b1);
                mma16816(sacc[nt], &qlo[kc * 4], b0, b1);
                u32 e0 = *(const u32*)&sKlo[n][kk];
                u32 e1 = *(const u32*)&sKlo[n][kk + 8];
                mma16816(sacc[nt], &qhi[kc * 4], e0, e1);
            }
        }

        // ---- softmax (exp2 domain) + PV per 16-token chunk
        #pragma unroll
        for (int kcp = 0; kcp < 4; kcp++) {
            u32 pah[4], pal[4];
            #pragma unroll
            for (int half = 0; half < 2; half++) {
                const int nt = kcp * 2 + half;
                const float jb = (float)(kbase + nt * 8 + 2 * c);
                float d00 = fi0 - jb, d01 = d00 - 1.0f;
                float d10 = fi1 - jb, d11 = d10 - 1.0f;
                float p00 = ex2f(fmaf(-rC * d00, d00, sacc[nt][0]));
                float p01 = ex2f(fmaf(-rC * d01, d01, sacc[nt][1]));
                float p10 = ex2f(fmaf(-rC * d10, d10, sacc[nt][2]));
                float p11 = ex2f(fmaf(-rC * d11, d11, sacc[nt][3]));
                l0 += p00 + p01;
                l1 += p10 + p11;
                split2(p00, p01, pah[half * 2 + 0], pal[half * 2 + 0]);
                split2(p10, p11, pah[half * 2 + 1], pal[half * 2 + 1]);
            }
            const int kk = kcp * 16 + 2 * c;
            #pragma unroll
            for (int ntv = 0; ntv < 8; ntv++) {
                const int dd = ntv * 8 + r;
                u32 b0 = *(const u32*)&sVhi[dd][kk];
                u32 b1 = *(const u32*)&sVhi[dd][kk + 8];
                mma16816(oacc[ntv], pah, b0, b1);
                mma16816(oacc[ntv], pal, b0, b1);
                u32 e0 = *(const u32*)&sVlo[dd][kk];
                u32 e1 = *(const u32*)&sVlo[dd][kk + 8];
                mma16816(oacc[ntv], pah, e0, e1);
            }
        }
    }

    // ---- reduce l across the 4 lanes of each row group, normalize, store
    l0 += __shfl_xor_sync(0xffffffffu, l0, 1);
    l0 += __shfl_xor_sync(0xffffffffu, l0, 2);
    l1 += __shfl_xor_sync(0xffffffffu, l1, 1);
    l1 += __shfl_xor_sync(0xffffffffu, l1, 2);
    const float inv0 = 1.0f / l0;
    const float inv1 = 1.0f / l1;

    const int row0 = qbase + warp * 16 + r;
    float* g0 = g_ctx + ((size_t)bb * SEQ + row0) * HID + hh * HDIM + 2 * c;
    float* g1 = g0 + 8 * HID;
    #pragma unroll
    for (int ntv = 0; ntv < 8; ntv++) {
        *(float2*)(g0 + ntv * 8) = make_float2(oacc[ntv][0] * inv0, oacc[ntv][1] * inv0);
        *(float2*)(g1 + ntv * 8) = make_float2(oacc[ntv][2] * inv1, oacc[ntv][3] * inv1);
    }
}

// ---------------------------------------------------------------------------
// out = ctx @ W^T + b  (M=8192, N=512, K=512) — scalar fp32, 128x128 tiles
// ---------------------------------------------------------------------------
__global__ void __launch_bounds__(256, 2)
proj_kernel(const float* __restrict__ W, const float* __restrict__ bias,
            float* __restrict__ out)
{
    __shared__ __align__(16) float As[16][132];
    __shared__ __align__(16) float Bs[16][132];

    const int mbase = blockIdx.x * 128;
    const int nbase = blockIdx.y * 128;
    const int tid = threadIdx.x;
    const int tx = tid & 15;
    const int ty = tid >> 4;

    float acc[8][8];
    #pragma unroll
    for (int i = 0; i < 8; i++)
        #pragma unroll
        for (int j = 0; j < 8; j++) acc[i][j] = 0.0f;

    for (int kt = 0; kt < HID / 16; kt++) {
        const int k0 = kt * 16;
        __syncthreads();
        #pragma unroll
        for (int u = 0; u < 2; u++) {
            int f  = u * 256 + tid;
            int rr = f >> 2;
            int cf = (f & 3) * 4;
            float4 a = *(const float4*)&g_ctx[(size_t)(mbase + rr) * HID + k0 + cf];
            As[cf + 0][rr] = a.x; As[cf + 1][rr] = a.y;
            As[cf + 2][rr] = a.z; As[cf + 3][rr] = a.w;
            float4 w = *(const float4*)&W[(size_t)(nbase + rr) * HID + k0 + cf];
            Bs[cf + 0][rr] = w.x; Bs[cf + 1][rr] = w.y;
            Bs[cf + 2][rr] = w.z; Bs[cf + 3][rr] = w.w;
        }
        __syncthreads();

        #pragma unroll
        for (int k = 0; k < 16; k++) {
            float4 a0 = *(const float4*)&As[k][ty * 8];
            float4 a1 = *(const float4*)&As[k][ty * 8 + 4];
            float4 b0 = *(const float4*)&Bs[k][tx * 8];
            float4 b1 = *(const float4*)&Bs[k][tx * 8 + 4];
            float af[8] = {a0.x, a0.y, a0.z, a0.w, a1.x, a1.y, a1.z, a1.w};
            float bf[8] = {b0.x, b0.y, b0.z, b0.w, b1.x, b1.y, b1.z, b1.w};
            #pragma unroll
            for (int i = 0; i < 8; i++)
                #pragma unroll
                for (int j = 0; j < 8; j++)
                    acc[i][j] = fmaf(af[i], bf[j], acc[i][j]);
        }
    }

    const int n0 = nbase + tx * 8;
    float4 b0 = *(const float4*)&bias[n0];
    float4 b1 = *(const float4*)&bias[n0 + 4];
    #pragma unroll
    for (int i = 0; i < 8; i++) {
        int m = mbase + ty * 8 + i;
        float4 o0 = make_float4(acc[i][0] + b0.x, acc[i][1] + b0.y,
                                acc[i][2] + b0.z, acc[i][3] + b0.w);
        float4 o1 = make_float4(acc[i][4] + b1.x, acc[i][5] + b1.y,
                                acc[i][6] + b1.z, acc[i][7] + b1.w);
        *(float4*)&out[(size_t)m * HID + n0]     = o0;
        *(float4*)&out[(size_t)m * HID + n0 + 4] = o1;
    }
}

extern "C" void kernel_launch(void* const* d_in, const int* in_sizes, int n_in,
                              void* d_out, int out_size)
{
    const float* Q     = (const float*)d_in[0];
    const float* K     = (const float*)d_in[1];
    const float* V     = (const float*)d_in[2];
    const float* sigma = (const float*)d_in[3];
    const float* lam   = (const float*)d_in[4];
    const float* W     = (const float*)d_in[5];
    const float* bias  = (const float*)d_in[6];
    float* out = (float*)d_out;

    dim3 g1(SEQ / BM, NB * NHEAD);
    attn_kernel<<<g1, 256>>>(Q, K, V, sigma, lam);

    dim3 g2(NB * SEQ / 128, HID / 128);
    proj_kernel<<<g2, 256>>>(W, bias, out);
}

// round 5
// speedup vs baseline: 3.3811x; 1.4579x over previous
#include <cuda_runtime.h>
#include <cuda_fp16.h>
#include <cstdint>

#define NB    2
#define SEQ   4096
#define HID   512
#define NHEAD 8
#define HDIM  64
#define BM    128
#define BN    64
#define NITER (SEQ / BN)
#define L2E   1.44269504088896340736f

typedef unsigned int u32;

// pack two floats -> half2 word (a in low half)
__device__ __forceinline__ u32 pack2h(float a, float b) {
    __half2 h = __floats2half2_rn(a, b);
    return *(u32*)&h;
}
// split pair (a,b) -> half2 hi word + half2 residual word
__device__ __forceinline__ void split2h(float a, float b, u32& hw, u32& lw) {
    __half ha = __float2half_rn(a), hb = __float2half_rn(b);
    float ra = a - __half2float(ha);
    float rb = b - __half2float(hb);
    __half2 hv; hv.x = ha; hv.y = hb;
    __half2 lv; lv.x = __float2half_rn(ra); lv.y = __float2half_rn(rb);
    hw = *(u32*)&hv; lw = *(u32*)&lv;
}

__device__ __forceinline__ float ex2f(float x) {
    float y; asm("ex2.approx.ftz.f32 %0, %1;" : "=f"(y) : "f"(x)); return y;
}

// D += A @ B  (m16n8k16, fp16 in, fp32 acc)
__device__ __forceinline__ void mma16816(float* c, const u32* a, u32 b0, u32 b1) {
    asm volatile(
        "mma.sync.aligned.m16n8k16.row.col.f32.f16.f16.f32 "
        "{%0,%1,%2,%3}, {%4,%5,%6,%7}, {%8,%9}, {%0,%1,%2,%3};"
        : "+f"(c[0]), "+f"(c[1]), "+f"(c[2]), "+f"(c[3])
        : "r"(a[0]), "r"(a[1]), "r"(a[2]), "r"(a[3]), "r"(b0), "r"(b1));
}

__device__ float g_ctx[NB * SEQ * HID];

#define KSTR 72   // halfs per row: fragment LDS conflict-free (4n+c)

// ---------------------------------------------------------------------------
// Flash attention: QK = Qhi*K + Qlo*K; PV = Phi*V + Plo*V (all fp16 HMMA,
// fp32 accum). No-max softmax (shift-invariant; scores bounded).
// Grid (SEQ/BM, NB*NHEAD), 256 thr. Warp w owns q-rows [w*16, w*16+16).
// Register prefetch of next K/V tile hides LDG latency under MMAs.
// ---------------------------------------------------------------------------
__global__ void __launch_bounds__(256, 1)
attn_kernel(const float* __restrict__ Q, const float* __restrict__ K,
            const float* __restrict__ V, const float* __restrict__ sigma,
            const float* __restrict__ lam_p)
{
    __shared__ __align__(16) __half sK[BN][KSTR];     // [token][d]
    __shared__ __align__(16) __half sV[HDIM][KSTR];   // [d][token]

    const int tid  = threadIdx.x;
    const int warp = tid >> 5;
    const int lane = tid & 31;
    const int r    = lane >> 2;
    const int c    = lane & 3;

    const int bb = blockIdx.y >> 3;
    const int hh = blockIdx.y & 7;
    const int qbase = blockIdx.x * BM;

    float sc = fminf(fmaxf(sigma[bb], 0.001f), 0.2f);
    float sn = (sc - 0.001f) * (1.0f / 0.199f);
    const float rC = lam_p[0] * 0.1f * sn * (1.0f / ((float)SEQ * (float)SEQ)) * L2E;

    const float* Qb = Q + (size_t)bb * SEQ * HID + hh * HDIM;
    const float* Kb = K + (size_t)bb * SEQ * HID + hh * HDIM;
    const float* Vb = V + (size_t)bb * SEQ * HID + hh * HDIM;

    // staging geometry (constant across tiles)
    const int k_tok  = tid >> 2;          // K: token row
    const int k_part = tid & 3;           // K: 16-d slice
    const int v_p    = tid & 31;          // V: token pair
    const int v_d0   = (tid >> 5) * 8;    // V: 8 d's

    // ---- Q fragments (persistent): hi + lo fp16, scaled by 0.125*log2e
    u32 qhi[16], qlo[16];
    {
        const float s = 0.125f * L2E;
        const int row0 = qbase + warp * 16 + r;
        const float* q0 = Qb + (size_t)row0 * HID;
        const float* q1 = q0 + 8 * HID;
        #pragma unroll
        for (int kc = 0; kc < 4; kc++) {
            int d = kc * 16 + 2 * c;
            split2h(q0[d] * s,     q0[d + 1] * s, qhi[kc * 4 + 0], qlo[kc * 4 + 0]);
            split2h(q1[d] * s,     q1[d + 1] * s, qhi[kc * 4 + 1], qlo[kc * 4 + 1]);
            split2h(q0[d + 8] * s, q0[d + 9] * s, qhi[kc * 4 + 2], qlo[kc * 4 + 2]);
            split2h(q1[d + 8] * s, q1[d + 9] * s, qhi[kc * 4 + 3], qlo[kc * 4 + 3]);
        }
    }

    float oacc[8][4];
    #pragma unroll
    for (int i = 0; i < 8; i++)
        #pragma unroll
        for (int j = 0; j < 4; j++) oacc[i][j] = 0.0f;
    float l0 = 0.0f, l1 = 0.0f;

    const float fi0 = (float)(qbase + warp * 16 + r);
    const float fi1 = fi0 + 8.0f;

    // ---- prefetch tile 0 (raw fp32) into registers
    float4 kreg[4], vreg[4];
    {
        const float* kr = Kb + (size_t)k_tok * HID + k_part * 16;
        #pragma unroll
        for (int i = 0; i < 4; i++) kreg[i] = ((const float4*)kr)[i];
        const float* v0 = Vb + (size_t)(2 * v_p) * HID + v_d0;
        const float* v1 = v0 + HID;
        vreg[0] = ((const float4*)v0)[0]; vreg[1] = ((const float4*)v1)[0];
        vreg[2] = ((const float4*)v0)[1]; vreg[3] = ((const float4*)v1)[1];
    }

    for (int kt = 0; kt < NITER; kt++) {
        const int kbase = kt * BN;
        __syncthreads();   // previous tile's fragment reads done

        // ---- convert prefetched regs -> fp16 SMEM tiles
        #pragma unroll
        for (int i = 0; i < 4; i++) {
            float4 v = kreg[i];
            int d = k_part * 16 + i * 4;
            *(u32*)&sK[k_tok][d]     = pack2h(v.x, v.y);
            *(u32*)&sK[k_tok][d + 2] = pack2h(v.z, v.w);
        }
        #pragma unroll
        for (int i = 0; i < 2; i++) {
            float4 a = vreg[2 * i];
            float4 b = vreg[2 * i + 1];
            float av[4] = {a.x, a.y, a.z, a.w};
            float bv[4] = {b.x, b.y, b.z, b.w};
            #pragma unroll
            for (int k2 = 0; k2 < 4; k2++) {
                int d = v_d0 + i * 4 + k2;
                *(u32*)&sV[d][2 * v_p] = pack2h(av[k2], bv[k2]);
            }
        }
        __syncthreads();

        // ---- issue next tile's LDGs (drain under the MMA phase below)
        if (kt + 1 < NITER) {
            const int nb2 = kbase + BN;
            const float* kr = Kb + (size_t)(nb2 + k_tok) * HID + k_part * 16;
            #pragma unroll
            for (int i = 0; i < 4; i++) kreg[i] = ((const float4*)kr)[i];
            const float* v0 = Vb + (size_t)(nb2 + 2 * v_p) * HID + v_d0;
            const float* v1 = v0 + HID;
            vreg[0] = ((const float4*)v0)[0]; vreg[1] = ((const float4*)v1)[0];
            vreg[2] = ((const float4*)v0)[1]; vreg[3] = ((const float4*)v1)[1];
        }

        // ---- S = Qhi*K + Qlo*K  (B-frags loaded once, used twice)
        float sacc[8][4];
        #pragma unroll
        for (int i = 0; i < 8; i++)
            #pragma unroll
            for (int j = 0; j < 4; j++) sacc[i][j] = 0.0f;

        #pragma unroll
        for (int kc = 0; kc < 4; kc++) {
            const int kk = kc * 16 + 2 * c;
            #pragma unroll
            for (int nt = 0; nt < 8; nt++) {
                const int n = nt * 8 + r;
                u32 b0 = *(const u32*)&sK[n][kk];
                u32 b1 = *(const u32*)&sK[n][kk + 8];
                mma16816(sacc[nt], &qhi[kc * 4], b0, b1);
                mma16816(sacc[nt], &qlo[kc * 4], b0, b1);
            }
        }

        // ---- softmax (exp2 domain) + PV per 16-token chunk
        #pragma unroll
        for (int kcp = 0; kcp < 4; kcp++) {
            u32 pah[4], pal[4];
            #pragma unroll
            for (int half = 0; half < 2; half++) {
                const int nt = kcp * 2 + half;
                const float jb = (float)(kbase + nt * 8 + 2 * c);
                float d00 = fi0 - jb, d01 = d00 - 1.0f;
                float d10 = fi1 - jb, d11 = d10 - 1.0f;
                float p00 = ex2f(fmaf(-rC * d00, d00, sacc[nt][0]));
                float p01 = ex2f(fmaf(-rC * d01, d01, sacc[nt][1]));
                float p10 = ex2f(fmaf(-rC * d10, d10, sacc[nt][2]));
                float p11 = ex2f(fmaf(-rC * d11, d11, sacc[nt][3]));
                l0 += p00 + p01;
                l1 += p10 + p11;
                split2h(p00, p01, pah[half * 2 + 0], pal[half * 2 + 0]);
                split2h(p10, p11, pah[half * 2 + 1], pal[half * 2 + 1]);
            }
            const int kk = kcp * 16 + 2 * c;
            #pragma unroll
            for (int ntv = 0; ntv < 8; ntv++) {
                const int dd = ntv * 8 + r;
                u32 b0 = *(const u32*)&sV[dd][kk];
                u32 b1 = *(const u32*)&sV[dd][kk + 8];
                mma16816(oacc[ntv], pah, b0, b1);
                mma16816(oacc[ntv], pal, b0, b1);
            }
        }
    }

    // ---- reduce l across the 4 lanes of each row group, normalize, store
    l0 += __shfl_xor_sync(0xffffffffu, l0, 1);
    l0 += __shfl_xor_sync(0xffffffffu, l0, 2);
    l1 += __shfl_xor_sync(0xffffffffu, l1, 1);
    l1 += __shfl_xor_sync(0xffffffffu, l1, 2);
    const float inv0 = 1.0f / l0;
    const float inv1 = 1.0f / l1;

    const int row0 = qbase + warp * 16 + r;
    float* g0 = g_ctx + ((size_t)bb * SEQ + row0) * HID + hh * HDIM + 2 * c;
    float* g1 = g0 + 8 * HID;
    #pragma unroll
    for (int ntv = 0; ntv < 8; ntv++) {
        *(float2*)(g0 + ntv * 8) = make_float2(oacc[ntv][0] * inv0, oacc[ntv][1] * inv0);
        *(float2*)(g1 + ntv * 8) = make_float2(oacc[ntv][2] * inv1, oacc[ntv][3] * inv1);
    }
}

// ---------------------------------------------------------------------------
// out = ctx @ W^T + b  (M=8192, N=512, K=512) — scalar fp32, 128x128 tiles
// ---------------------------------------------------------------------------
__global__ void __launch_bounds__(256, 2)
proj_kernel(const float* __restrict__ W, const float* __restrict__ bias,
            float* __restrict__ out)
{
    __shared__ __align__(16) float As[16][132];
    __shared__ __align__(16) float Bs[16][132];

    const int mbase = blockIdx.x * 128;
    const int nbase = blockIdx.y * 128;
    const int tid = threadIdx.x;
    const int tx = tid & 15;
    const int ty = tid >> 4;

    float acc[8][8];
    #pragma unroll
    for (int i = 0; i < 8; i++)
        #pragma unroll
        for (int j = 0; j < 8; j++) acc[i][j] = 0.0f;

    for (int kt = 0; kt < HID / 16; kt++) {
        const int k0 = kt * 16;
        __syncthreads();
        #pragma unroll
        for (int u = 0; u < 2; u++) {
            int f  = u * 256 + tid;
            int rr = f >> 2;
            int cf = (f & 3) * 4;
            float4 a = *(const float4*)&g_ctx[(size_t)(mbase + rr) * HID + k0 + cf];
            As[cf + 0][rr] = a.x; As[cf + 1][rr] = a.y;
            As[cf + 2][rr] = a.z; As[cf + 3][rr] = a.w;
            float4 w = *(const float4*)&W[(size_t)(nbase + rr) * HID + k0 + cf];
            Bs[cf + 0][rr] = w.x; Bs[cf + 1][rr] = w.y;
            Bs[cf + 2][rr] = w.z; Bs[cf + 3][rr] = w.w;
        }
        __syncthreads();

        #pragma unroll
        for (int k = 0; k < 16; k++) {
            float4 a0 = *(const float4*)&As[k][ty * 8];
            float4 a1 = *(const float4*)&As[k][ty * 8 + 4];
            float4 b0 = *(const float4*)&Bs[k][tx * 8];
            float4 b1 = *(const float4*)&Bs[k][tx * 8 + 4];
            float af[8] = {a0.x, a0.y, a0.z, a0.w, a1.x, a1.y, a1.z, a1.w};
            float bf[8] = {b0.x, b0.y, b0.z, b0.w, b1.x, b1.y, b1.z, b1.w};
            #pragma unroll
            for (int i = 0; i < 8; i++)
                #pragma unroll
                for (int j = 0; j < 8; j++)
                    acc[i][j] = fmaf(af[i], bf[j], acc[i][j]);
        }
    }

    const int n0 = nbase + tx * 8;
    float4 b0 = *(const float4*)&bias[n0];
    float4 b1 = *(const float4*)&bias[n0 + 4];
    #pragma unroll
    for (int i = 0; i < 8; i++) {
        int m = mbase + ty * 8 + i;
        float4 o0 = make_float4(acc[i][0] + b0.x, acc[i][1] + b0.y,
                                acc[i][2] + b0.z, acc[i][3] + b0.w);
        float4 o1 = make_float4(acc[i][4] + b1.x, acc[i][5] + b1.y,
                                acc[i][6] + b1.z, acc[i][7] + b1.w);
        *(float4*)&out[(size_t)m * HID + n0]     = o0;
        *(float4*)&out[(size_t)m * HID + n0 + 4] = o1;
    }
}

extern "C" void kernel_launch(void* const* d_in, const int* in_sizes, int n_in,
                              void* d_out, int out_size)
{
    const float* Q     = (const float*)d_in[0];
    const float* K     = (const float*)d_in[1];
    const float* V     = (const float*)d_in[2];
    const float* sigma = (const float*)d_in[3];
    const float* lam   = (const float*)d_in[4];
    const float* W     = (const float*)d_in[5];
    const float* bias  = (const float*)d_in[6];
    float* out = (float*)d_out;

    dim3 g1(SEQ / BM, NB * NHEAD);
    attn_kernel<<<g1, 256>>>(Q, K, V, sigma, lam);

    dim3 g2(NB * SEQ / 128, HID / 128);
    proj_kernel<<<g2, 256>>>(W, bias, out);
}

// round 6
// speedup vs baseline: 3.9904x; 1.1802x over previous
#include <cuda_runtime.h>
#include <cuda_fp16.h>
#include <cstdint>

#define NB    2
#define SEQ   4096
#define HID   512
#define NHEAD 8
#define HDIM  64
#define BM    128
#define BN    64
#define NITER (SEQ / BN)
#define L2E   1.44269504088896340736f

typedef unsigned int u32;

__device__ __forceinline__ u32 pack2h(float a, float b) {
    __half2 h = __floats2half2_rn(a, b);
    return *(u32*)&h;
}
__device__ __forceinline__ void split2h(float a, float b, u32& hw, u32& lw) {
    __half ha = __float2half_rn(a), hb = __float2half_rn(b);
    float ra = a - __half2float(ha);
    float rb = b - __half2float(hb);
    __half2 hv; hv.x = ha; hv.y = hb;
    __half2 lv; lv.x = __float2half_rn(ra); lv.y = __float2half_rn(rb);
    hw = *(u32*)&hv; lw = *(u32*)&lv;
}
__device__ __forceinline__ float ex2f(float x) {
    float y; asm("ex2.approx.ftz.f32 %0, %1;" : "=f"(y) : "f"(x)); return y;
}
// D += A @ B  (m16n8k16, fp16 in, fp32 acc)
__device__ __forceinline__ void mma16816(float* c, const u32* a, u32 b0, u32 b1) {
    asm volatile(
        "mma.sync.aligned.m16n8k16.row.col.f32.f16.f16.f32 "
        "{%0,%1,%2,%3}, {%4,%5,%6,%7}, {%8,%9}, {%0,%1,%2,%3};"
        : "+f"(c[0]), "+f"(c[1]), "+f"(c[2]), "+f"(c[3])
        : "r"(a[0]), "r"(a[1]), "r"(a[2]), "r"(a[3]), "r"(b0), "r"(b1));
}

__device__ float g_ctx[NB * SEQ * HID];

#define KSTR 72   // halfs per row: fragment LDS conflict-free (4n+c)

// ---------------------------------------------------------------------------
// Flash attention: QK = (Qhi+Qlo)*K (2 passes); PV = Phi*V (1 pass).
// No-max softmax (shift-invariant; scores bounded). occ=2 hides staging /
// softmax of one CTA under the other CTA's HMMAs.
// ---------------------------------------------------------------------------
__global__ void __launch_bounds__(256, 2)
attn_kernel(const float* __restrict__ Q, const float* __restrict__ K,
            const float* __restrict__ V, const float* __restrict__ sigma,
            const float* __restrict__ lam_p)
{
    __shared__ __align__(16) __half sK[BN][KSTR];     // [token][d]
    __shared__ __align__(16) __half sV[HDIM][KSTR];   // [d][token]

    const int tid  = threadIdx.x;
    const int warp = tid >> 5;
    const int lane = tid & 31;
    const int r    = lane >> 2;
    const int c    = lane & 3;

    const int bb = blockIdx.y >> 3;
    const int hh = blockIdx.y & 7;
    const int qbase = blockIdx.x * BM;

    float sc = fminf(fmaxf(sigma[bb], 0.001f), 0.2f);
    float sn = (sc - 0.001f) * (1.0f / 0.199f);
    const float rC = lam_p[0] * 0.1f * sn * (1.0f / ((float)SEQ * (float)SEQ)) * L2E;

    const float* Qb = Q + (size_t)bb * SEQ * HID + hh * HDIM;
    const float* Kb = K + (size_t)bb * SEQ * HID + hh * HDIM;
    const float* Vb = V + (size_t)bb * SEQ * HID + hh * HDIM;

    const int k_tok  = tid >> 2;          // K staging: token row
    const int k_part = tid & 3;           // K staging: 16-d slice
    const int v_p    = tid & 31;          // V staging: token pair
    const int v_d0   = (tid >> 5) * 8;    // V staging: 8 d's

    // ---- Q fragments (persistent): hi + lo fp16, scaled by 0.125*log2e
    u32 qhi[16], qlo[16];
    {
        const float s = 0.125f * L2E;
        const int row0 = qbase + warp * 16 + r;
        const float* q0 = Qb + (size_t)row0 * HID;
        const float* q1 = q0 + 8 * HID;
        #pragma unroll
        for (int kc = 0; kc < 4; kc++) {
            int d = kc * 16 + 2 * c;
            split2h(q0[d] * s,     q0[d + 1] * s, qhi[kc * 4 + 0], qlo[kc * 4 + 0]);
            split2h(q1[d] * s,     q1[d + 1] * s, qhi[kc * 4 + 1], qlo[kc * 4 + 1]);
            split2h(q0[d + 8] * s, q0[d + 9] * s, qhi[kc * 4 + 2], qlo[kc * 4 + 2]);
            split2h(q1[d + 8] * s, q1[d + 9] * s, qhi[kc * 4 + 3], qlo[kc * 4 + 3]);
        }
    }

    float oacc[8][4];
    #pragma unroll
    for (int i = 0; i < 8; i++)
        #pragma unroll
        for (int j = 0; j < 4; j++) oacc[i][j] = 0.0f;
    float l0 = 0.0f, l1 = 0.0f;

    const float fi0 = (float)(qbase + warp * 16 + r);
    const float fi1 = fi0 + 8.0f;

    for (int kt = 0; kt < NITER; kt++) {
        const int kbase = kt * BN;
        __syncthreads();   // previous tile's fragment reads done

        // ---- stage K tile [64 tok x 64 d] -> fp16 SMEM (token-major)
        {
            const float* kr = Kb + (size_t)(kbase + k_tok) * HID + k_part * 16;
            #pragma unroll
            for (int i = 0; i < 4; i++) {
                float4 v = ((const float4*)kr)[i];
                int d = k_part * 16 + i * 4;
                *(u32*)&sK[k_tok][d]     = pack2h(v.x, v.y);
                *(u32*)&sK[k_tok][d + 2] = pack2h(v.z, v.w);
            }
        }
        // ---- stage V^T tile [64 d x 64 tok] (token pairs packed in u32)
        {
            const float* v0 = Vb + (size_t)(kbase + 2 * v_p) * HID + v_d0;
            const float* v1 = v0 + HID;
            #pragma unroll
            for (int i = 0; i < 2; i++) {
                float4 a = ((const float4*)v0)[i];
                float4 b = ((const float4*)v1)[i];
                float av[4] = {a.x, a.y, a.z, a.w};
                float bv[4] = {b.x, b.y, b.z, b.w};
                #pragma unroll
                for (int k2 = 0; k2 < 4; k2++) {
                    int d = v_d0 + i * 4 + k2;
                    *(u32*)&sV[d][2 * v_p] = pack2h(av[k2], bv[k2]);
                }
            }
        }
        __syncthreads();

        // ---- S = Qhi*K + Qlo*K  (B-frags loaded once, used twice)
        float sacc[8][4];
        #pragma unroll
        for (int i = 0; i < 8; i++)
            #pragma unroll
            for (int j = 0; j < 4; j++) sacc[i][j] = 0.0f;

        #pragma unroll
        for (int kc = 0; kc < 4; kc++) {
            const int kk = kc * 16 + 2 * c;
            #pragma unroll
            for (int nt = 0; nt < 8; nt++) {
                const int n = nt * 8 + r;
                u32 b0 = *(const u32*)&sK[n][kk];
                u32 b1 = *(const u32*)&sK[n][kk + 8];
                mma16816(sacc[nt], &qhi[kc * 4], b0, b1);
                mma16816(sacc[nt], &qlo[kc * 4], b0, b1);
            }
        }

        // ---- softmax (exp2 domain) + PV (single fp16 pass)
        #pragma unroll
        for (int kcp = 0; kcp < 4; kcp++) {
            u32 pah[4];
            #pragma unroll
            for (int half = 0; half < 2; half++) {
                const int nt = kcp * 2 + half;
                const float jb = (float)(kbase + nt * 8 + 2 * c);
                float d00 = fi0 - jb, d01 = d00 - 1.0f;
                float d10 = fi1 - jb, d11 = d10 - 1.0f;
                float p00 = ex2f(fmaf(-rC * d00, d00, sacc[nt][0]));
                float p01 = ex2f(fmaf(-rC * d01, d01, sacc[nt][1]));
                float p10 = ex2f(fmaf(-rC * d10, d10, sacc[nt][2]));
                float p11 = ex2f(fmaf(-rC * d11, d11, sacc[nt][3]));
                l0 += p00 + p01;
                l1 += p10 + p11;
                pah[half * 2 + 0] = pack2h(p00, p01);
                pah[half * 2 + 1] = pack2h(p10, p11);
            }
            const int kk = kcp * 16 + 2 * c;
            #pragma unroll
            for (int ntv = 0; ntv < 8; ntv++) {
                const int dd = ntv * 8 + r;
                u32 b0 = *(const u32*)&sV[dd][kk];
                u32 b1 = *(const u32*)&sV[dd][kk + 8];
                mma16816(oacc[ntv], pah, b0, b1);
            }
        }
    }

    // ---- reduce l across the 4 lanes of each row group, normalize, store
    l0 += __shfl_xor_sync(0xffffffffu, l0, 1);
    l0 += __shfl_xor_sync(0xffffffffu, l0, 2);
    l1 += __shfl_xor_sync(0xffffffffu, l1, 1);
    l1 += __shfl_xor_sync(0xffffffffu, l1, 2);
    const float inv0 = 1.0f / l0;
    const float inv1 = 1.0f / l1;

    const int row0 = qbase + warp * 16 + r;
    float* g0 = g_ctx + ((size_t)bb * SEQ + row0) * HID + hh * HDIM + 2 * c;
    float* g1 = g0 + 8 * HID;
    #pragma unroll
    for (int ntv = 0; ntv < 8; ntv++) {
        *(float2*)(g0 + ntv * 8) = make_float2(oacc[ntv][0] * inv0, oacc[ntv][1] * inv0);
        *(float2*)(g1 + ntv * 8) = make_float2(oacc[ntv][2] * inv1, oacc[ntv][3] * inv1);
    }
}

// ---------------------------------------------------------------------------
// out = ctx @ W^T + b  (M=8192, N=512, K=512) — split-fp16 HMMA:
// out = (ctx_hi + ctx_lo) @ W16^T. 128x128 tile, 8 warps (4m x 2n).
// ---------------------------------------------------------------------------
#define PCH 32
#define PSTR 40   // halfs per row: frag LDS conflict-free (20r+8kf+c distinct)

__global__ void __launch_bounds__(256, 2)
proj_kernel(const float* __restrict__ W, const float* __restrict__ bias,
            float* __restrict__ out)
{
    __shared__ __align__(16) __half sAhi[128][PSTR];
    __shared__ __align__(16) __half sAlo[128][PSTR];
    __shared__ __align__(16) __half sW[128][PSTR];

    const int tid  = threadIdx.x;
    const int warp = tid >> 5;
    const int lane = tid & 31;
    const int r    = lane >> 2;
    const int c    = lane & 3;
    const int mw   = warp & 3;    // m 32-slab
    const int nw   = warp >> 2;   // n 64-slab

    const int mbase = blockIdx.x * 128;
    const int nbase = blockIdx.y * 128;

    const int r2 = tid >> 1;           // staging row
    const int h2 = (tid & 1) * 16;     // staging k-half

    float acc[2][8][4];
    #pragma unroll
    for (int mf = 0; mf < 2; mf++)
        #pragma unroll
        for (int nf = 0; nf < 8; nf++)
            #pragma unroll
            for (int j = 0; j < 4; j++) acc[mf][nf][j] = 0.0f;

    for (int kc = 0; kc < HID / PCH; kc++) {
        const int k0 = kc * PCH;
        __syncthreads();
        // ---- stage ctx (split hi/lo) and W (fp16)
        {
            const float* ar = g_ctx + (size_t)(mbase + r2) * HID + k0 + h2;
            #pragma unroll
            for (int i = 0; i < 4; i++) {
                float4 v = ((const float4*)ar)[i];
                u32 hw, lw;
                split2h(v.x, v.y, hw, lw);
                *(u32*)&sAhi[r2][h2 + i * 4]     = hw;
                *(u32*)&sAlo[r2][h2 + i * 4]     = lw;
                split2h(v.z, v.w, hw, lw);
                *(u32*)&sAhi[r2][h2 + i * 4 + 2] = hw;
                *(u32*)&sAlo[r2][h2 + i * 4 + 2] = lw;
            }
            const float* wr = W + (size_t)(nbase + r2) * HID + k0 + h2;
            #pragma unroll
            for (int i = 0; i < 4; i++) {
                float4 v = ((const float4*)wr)[i];
                *(u32*)&sW[r2][h2 + i * 4]     = pack2h(v.x, v.y);
                *(u32*)&sW[r2][h2 + i * 4 + 2] = pack2h(v.z, v.w);
            }
        }
        __syncthreads();

        #pragma unroll
        for (int kf = 0; kf < 2; kf++) {
            const int kk = kf * 16 + 2 * c;
            u32 ah[2][4], al[2][4];
            #pragma unroll
            for (int mf = 0; mf < 2; mf++) {
                const int m0 = mw * 32 + mf * 16;
                ah[mf][0] = *(const u32*)&sAhi[m0 + r][kk];
                ah[mf][1] = *(const u32*)&sAhi[m0 + r + 8][kk];
                ah[mf][2] = *(const u32*)&sAhi[m0 + r][kk + 8];
                ah[mf][3] = *(const u32*)&sAhi[m0 + r + 8][kk + 8];
                al[mf][0] = *(const u32*)&sAlo[m0 + r][kk];
                al[mf][1] = *(const u32*)&sAlo[m0 + r + 8][kk];
                al[mf][2] = *(const u32*)&sAlo[m0 + r][kk + 8];
                al[mf][3] = *(const u32*)&sAlo[m0 + r + 8][kk + 8];
            }
            #pragma unroll
            for (int nf = 0; nf < 8; nf++) {
                const int n0 = nw * 64 + nf * 8 + r;
                u32 b0 = *(const u32*)&sW[n0][kk];
                u32 b1 = *(const u32*)&sW[n0][kk + 8];
                mma16816(acc[0][nf], ah[0], b0, b1);
                mma16816(acc[0][nf], al[0], b0, b1);
                mma16816(acc[1][nf], ah[1], b0, b1);
                mma16816(acc[1][nf], al[1], b0, b1);
            }
        }
    }

    // ---- epilogue: + bias, fp32 out
    #pragma unroll
    for (int nf = 0; nf < 8; nf++) {
        const int n = nbase + nw * 64 + nf * 8 + 2 * c;
        const float bv0 = bias[n], bv1 = bias[n + 1];
        #pragma unroll
        for (int mf = 0; mf < 2; mf++) {
            const int m = mbase + mw * 32 + mf * 16 + r;
            *(float2*)&out[(size_t)m * HID + n] =
                make_float2(acc[mf][nf][0] + bv0, acc[mf][nf][1] + bv1);
            *(float2*)&out[(size_t)(m + 8) * HID + n] =
                make_float2(acc[mf][nf][2] + bv0, acc[mf][nf][3] + bv1);
        }
    }
}

extern "C" void kernel_launch(void* const* d_in, const int* in_sizes, int n_in,
                              void* d_out, int out_size)
{
    const float* Q     = (const float*)d_in[0];
    const float* K     = (const float*)d_in[1];
    const float* V     = (const float*)d_in[2];
    const float* sigma = (const float*)d_in[3];
    const float* lam   = (const float*)d_in[4];
    const float* W     = (const float*)d_in[5];
    const float* bias  = (const float*)d_in[6];
    float* out = (float*)d_out;

    dim3 g1(SEQ / BM, NB * NHEAD);
    attn_kernel<<<g1, 256>>>(Q, K, V, sigma, lam);

    dim3 g2(NB * SEQ / 128, HID / 128);
    proj_kernel<<<g2, 256>>>(W, bias, out);
}

// round 7
// speedup vs baseline: 4.4272x; 1.1095x over previous
#include <cuda_runtime.h>
#include <cuda_fp16.h>
#include <cstdint>

#define NB    2
#define SEQ   4096
#define HID   512
#define NHEAD 8
#define HDIM  64
#define BM    128
#define BN    64
#define NITER (SEQ / BN)
#define L2E   1.44269504088896340736f

typedef unsigned int u32;

__device__ __forceinline__ u32 pack2h(float a, float b) {
    __half2 h = __floats2half2_rn(a, b);
    return *(u32*)&h;
}
__device__ __forceinline__ void split2h(float a, float b, u32& hw, u32& lw) {
    __half ha = __float2half_rn(a), hb = __float2half_rn(b);
    float ra = a - __half2float(ha);
    float rb = b - __half2float(hb);
    __half2 hv; hv.x = ha; hv.y = hb;
    __half2 lv; lv.x = __float2half_rn(ra); lv.y = __float2half_rn(rb);
    hw = *(u32*)&hv; lw = *(u32*)&lv;
}
__device__ __forceinline__ float ex2f(float x) {
    float y; asm("ex2.approx.ftz.f32 %0, %1;" : "=f"(y) : "f"(x)); return y;
}
// D += A @ B  (m16n8k16, fp16 in, fp32 acc)
__device__ __forceinline__ void mma16816(float* c, const u32* a, u32 b0, u32 b1) {
    asm volatile(
        "mma.sync.aligned.m16n8k16.row.col.f32.f16.f16.f32 "
        "{%0,%1,%2,%3}, {%4,%5,%6,%7}, {%8,%9}, {%0,%1,%2,%3};"
        : "+f"(c[0]), "+f"(c[1]), "+f"(c[2]), "+f"(c[3])
        : "r"(a[0]), "r"(a[1]), "r"(a[2]), "r"(a[3]), "r"(b0), "r"(b1));
}

__device__ float g_ctx[NB * SEQ * HID];

#define KSTR 72   // halfs per row: fragment LDS conflict-free (4n+c)

// ---------------------------------------------------------------------------
// Flash attention: QK = Q16*K16 (1 pass); PV = P16*V16 (1 pass), fp32 acc.
// No-max softmax (shift-invariant; scores bounded). occ=2 hides staging /
// softmax of one CTA under the other CTA's HMMAs.
// ---------------------------------------------------------------------------
__global__ void __launch_bounds__(256, 2)
attn_kernel(const float* __restrict__ Q, const float* __restrict__ K,
            const float* __restrict__ V, const float* __restrict__ sigma,
            const float* __restrict__ lam_p)
{
    __shared__ __align__(16) __half sK[BN][KSTR];     // [token][d]
    __shared__ __align__(16) __half sV[HDIM][KSTR];   // [d][token]

    const int tid  = threadIdx.x;
    const int warp = tid >> 5;
    const int lane = tid & 31;
    const int r    = lane >> 2;
    const int c    = lane & 3;

    const int bb = blockIdx.y >> 3;
    const int hh = blockIdx.y & 7;
    const int qbase = blockIdx.x * BM;

    float sc = fminf(fmaxf(sigma[bb], 0.001f), 0.2f);
    float sn = (sc - 0.001f) * (1.0f / 0.199f);
    const float rC = lam_p[0] * 0.1f * sn * (1.0f / ((float)SEQ * (float)SEQ)) * L2E;

    const float* Qb = Q + (size_t)bb * SEQ * HID + hh * HDIM;
    const float* Kb = K + (size_t)bb * SEQ * HID + hh * HDIM;
    const float* Vb = V + (size_t)bb * SEQ * HID + hh * HDIM;

    const int k_tok  = tid >> 2;          // K staging: token row
    const int k_part = tid & 3;           // K staging: 16-d slice
    const int v_p    = tid & 31;          // V staging: token pair
    const int v_d0   = (tid >> 5) * 8;    // V staging: 8 d's

    // ---- Q fragments (persistent): fp16, scaled by 0.125*log2e
    u32 qf[16];
    {
        const float s = 0.125f * L2E;
        const int row0 = qbase + warp * 16 + r;
        const float* q0 = Qb + (size_t)row0 * HID;
        const float* q1 = q0 + 8 * HID;
        #pragma unroll
        for (int kc = 0; kc < 4; kc++) {
            int d = kc * 16 + 2 * c;
            qf[kc * 4 + 0] = pack2h(q0[d] * s,     q0[d + 1] * s);
            qf[kc * 4 + 1] = pack2h(q1[d] * s,     q1[d + 1] * s);
            qf[kc * 4 + 2] = pack2h(q0[d + 8] * s, q0[d + 9] * s);
            qf[kc * 4 + 3] = pack2h(q1[d + 8] * s, q1[d + 9] * s);
        }
    }

    float oacc[8][4];
    #pragma unroll
    for (int i = 0; i < 8; i++)
        #pragma unroll
        for (int j = 0; j < 4; j++) oacc[i][j] = 0.0f;
    float l0 = 0.0f, l1 = 0.0f;

    const float fi0 = (float)(qbase + warp * 16 + r);
    const float fi1 = fi0 + 8.0f;

    for (int kt = 0; kt < NITER; kt++) {
        const int kbase = kt * BN;
        __syncthreads();   // previous tile's fragment reads done

        // ---- stage K tile [64 tok x 64 d] -> fp16 SMEM (token-major)
        {
            const float* kr = Kb + (size_t)(kbase + k_tok) * HID + k_part * 16;
            #pragma unroll
            for (int i = 0; i < 4; i++) {
                float4 v = ((const float4*)kr)[i];
                int d = k_part * 16 + i * 4;
                *(u32*)&sK[k_tok][d]     = pack2h(v.x, v.y);
                *(u32*)&sK[k_tok][d + 2] = pack2h(v.z, v.w);
            }
        }
        // ---- stage V^T tile [64 d x 64 tok] (token pairs packed in u32)
        {
            const float* v0 = Vb + (size_t)(kbase + 2 * v_p) * HID + v_d0;
            const float* v1 = v0 + HID;
            #pragma unroll
            for (int i = 0; i < 2; i++) {
                float4 a = ((const float4*)v0)[i];
                float4 b = ((const float4*)v1)[i];
                float av[4] = {a.x, a.y, a.z, a.w};
                float bv[4] = {b.x, b.y, b.z, b.w};
                #pragma unroll
                for (int k2 = 0; k2 < 4; k2++) {
                    int d = v_d0 + i * 4 + k2;
                    *(u32*)&sV[d][2 * v_p] = pack2h(av[k2], bv[k2]);
                }
            }
        }
        __syncthreads();

        // ---- S = Q @ K^T  (single fp16 pass)
        float sacc[8][4];
        #pragma unroll
        for (int i = 0; i < 8; i++)
            #pragma unroll
            for (int j = 0; j < 4; j++) sacc[i][j] = 0.0f;

        #pragma unroll
        for (int kc = 0; kc < 4; kc++) {
            const int kk = kc * 16 + 2 * c;
            #pragma unroll
            for (int nt = 0; nt < 8; nt++) {
                const int n = nt * 8 + r;
                u32 b0 = *(const u32*)&sK[n][kk];
                u32 b1 = *(const u32*)&sK[n][kk + 8];
                mma16816(sacc[nt], &qf[kc * 4], b0, b1);
            }
        }

        // ---- softmax (exp2 domain) + PV (single fp16 pass)
        #pragma unroll
        for (int kcp = 0; kcp < 4; kcp++) {
            u32 pah[4];
            #pragma unroll
            for (int half = 0; half < 2; half++) {
                const int nt = kcp * 2 + half;
                const float jb = (float)(kbase + nt * 8 + 2 * c);
                float d00 = fi0 - jb, d01 = d00 - 1.0f;
                float d10 = fi1 - jb, d11 = d10 - 1.0f;
                float p00 = ex2f(fmaf(-rC * d00, d00, sacc[nt][0]));
                float p01 = ex2f(fmaf(-rC * d01, d01, sacc[nt][1]));
                float p10 = ex2f(fmaf(-rC * d10, d10, sacc[nt][2]));
                float p11 = ex2f(fmaf(-rC * d11, d11, sacc[nt][3]));
                l0 += p00 + p01;
                l1 += p10 + p11;
                pah[half * 2 + 0] = pack2h(p00, p01);
                pah[half * 2 + 1] = pack2h(p10, p11);
            }
            const int kk = kcp * 16 + 2 * c;
            #pragma unroll
            for (int ntv = 0; ntv < 8; ntv++) {
                const int dd = ntv * 8 + r;
                u32 b0 = *(const u32*)&sV[dd][kk];
                u32 b1 = *(const u32*)&sV[dd][kk + 8];
                mma16816(oacc[ntv], pah, b0, b1);
            }
        }
    }

    // ---- reduce l across the 4 lanes of each row group, normalize, store
    l0 += __shfl_xor_sync(0xffffffffu, l0, 1);
    l0 += __shfl_xor_sync(0xffffffffu, l0, 2);
    l1 += __shfl_xor_sync(0xffffffffu, l1, 1);
    l1 += __shfl_xor_sync(0xffffffffu, l1, 2);
    const float inv0 = 1.0f / l0;
    const float inv1 = 1.0f / l1;

    const int row0 = qbase + warp * 16 + r;
    float* g0 = g_ctx + ((size_t)bb * SEQ + row0) * HID + hh * HDIM + 2 * c;
    float* g1 = g0 + 8 * HID;
    #pragma unroll
    for (int ntv = 0; ntv < 8; ntv++) {
        *(float2*)(g0 + ntv * 8) = make_float2(oacc[ntv][0] * inv0, oacc[ntv][1] * inv0);
        *(float2*)(g1 + ntv * 8) = make_float2(oacc[ntv][2] * inv1, oacc[ntv][3] * inv1);
    }
}

// ---------------------------------------------------------------------------
// out = ctx @ W^T + b  (M=8192, N=512, K=512) — split-fp16 HMMA:
// out = (ctx_hi + ctx_lo) @ W16^T. 128x128 tile, 8 warps (4m x 2n).
// ---------------------------------------------------------------------------
#define PCH 32
#define PSTR 40

__global__ void __launch_bounds__(256, 2)
proj_kernel(const float* __restrict__ W, const float* __restrict__ bias,
            float* __restrict__ out)
{
    __shared__ __align__(16) __half sAhi[128][PSTR];
    __shared__ __align__(16) __half sAlo[128][PSTR];
    __shared__ __align__(16) __half sW[128][PSTR];

    const int tid  = threadIdx.x;
    const int warp = tid >> 5;
    const int lane = tid & 31;
    const int r    = lane >> 2;
    const int c    = lane & 3;
    const int mw   = warp & 3;
    const int nw   = warp >> 2;

    const int mbase = blockIdx.x * 128;
    const int nbase = blockIdx.y * 128;

    const int r2 = tid >> 1;
    const int h2 = (tid & 1) * 16;

    float acc[2][8][4];
    #pragma unroll
    for (int mf = 0; mf < 2; mf++)
        #pragma unroll
        for (int nf = 0; nf < 8; nf++)
            #pragma unroll
            for (int j = 0; j < 4; j++) acc[mf][nf][j] = 0.0f;

    for (int kc = 0; kc < HID / PCH; kc++) {
        const int k0 = kc * PCH;
        __syncthreads();
        {
            const float* ar = g_ctx + (size_t)(mbase + r2) * HID + k0 + h2;
            #pragma unroll
            for (int i = 0; i < 4; i++) {
                float4 v = ((const float4*)ar)[i];
                u32 hw, lw;
                split2h(v.x, v.y, hw, lw);
                *(u32*)&sAhi[r2][h2 + i * 4]     = hw;
                *(u32*)&sAlo[r2][h2 + i * 4]     = lw;
                split2h(v.z, v.w, hw, lw);
                *(u32*)&sAhi[r2][h2 + i * 4 + 2] = hw;
                *(u32*)&sAlo[r2][h2 + i * 4 + 2] = lw;
            }
            const float* wr = W + (size_t)(nbase + r2) * HID + k0 + h2;
            #pragma unroll
            for (int i = 0; i < 4; i++) {
                float4 v = ((const float4*)wr)[i];
                *(u32*)&sW[r2][h2 + i * 4]     = pack2h(v.x, v.y);
                *(u32*)&sW[r2][h2 + i * 4 + 2] = pack2h(v.z, v.w);
            }
        }
        __syncthreads();

        #pragma unroll
        for (int kf = 0; kf < 2; kf++) {
            const int kk = kf * 16 + 2 * c;
            u32 ah[2][4], al[2][4];
            #pragma unroll
            for (int mf = 0; mf < 2; mf++) {
                const int m0 = mw * 32 + mf * 16;
                ah[mf][0] = *(const u32*)&sAhi[m0 + r][kk];
                ah[mf][1] = *(const u32*)&sAhi[m0 + r + 8][kk];
                ah[mf][2] = *(const u32*)&sAhi[m0 + r][kk + 8];
                ah[mf][3] = *(const u32*)&sAhi[m0 + r + 8][kk + 8];
                al[mf][0] = *(const u32*)&sAlo[m0 + r][kk];
                al[mf][1] = *(const u32*)&sAlo[m0 + r + 8][kk];
                al[mf][2] = *(const u32*)&sAlo[m0 + r][kk + 8];
                al[mf][3] = *(const u32*)&sAlo[m0 + r + 8][kk + 8];
            }
            #pragma unroll
            for (int nf = 0; nf < 8; nf++) {
                const int n0 = nw * 64 + nf * 8 + r;
                u32 b0 = *(const u32*)&sW[n0][kk];
                u32 b1 = *(const u32*)&sW[n0][kk + 8];
                mma16816(acc[0][nf], ah[0], b0, b1);
                mma16816(acc[0][nf], al[0], b0, b1);
                mma16816(acc[1][nf], ah[1], b0, b1);
                mma16816(acc[1][nf], al[1], b0, b1);
            }
        }
    }

    #pragma unroll
    for (int nf = 0; nf < 8; nf++) {
        const int n = nbase + nw * 64 + nf * 8 + 2 * c;
        const float bv0 = bias[n], bv1 = bias[n + 1];
        #pragma unroll
        for (int mf = 0; mf < 2; mf++) {
            const int m = mbase + mw * 32 + mf * 16 + r;
            *(float2*)&out[(size_t)m * HID + n] =
                make_float2(acc[mf][nf][0] + bv0, acc[mf][nf][1] + bv1);
            *(float2*)&out[(size_t)(m + 8) * HID + n] =
                make_float2(acc[mf][nf][2] + bv0, acc[mf][nf][3] + bv1);
        }
    }
}

extern "C" void kernel_launch(void* const* d_in, const int* in_sizes, int n_in,
                              void* d_out, int out_size)
{
    const float* Q     = (const float*)d_in[0];
    const float* K     = (const float*)d_in[1];
    const float* V     = (const float*)d_in[2];
    const float* sigma = (const float*)d_in[3];
    const float* lam   = (const float*)d_in[4];
    const float* W     = (const float*)d_in[5];
    const float* bias  = (const float*)d_in[6];
    float* out = (float*)d_out;

    dim3 g1(SEQ / BM, NB * NHEAD);
    attn_kernel<<<g1, 256>>>(Q, K, V, sigma, lam);

    dim3 g2(NB * SEQ / 128, HID / 128);
    proj_kernel<<<g2, 256>>>(W, bias, out);
}

// round 8
// speedup vs baseline: 4.4896x; 1.0141x over previous
#include <cuda_runtime.h>
#include <cuda_fp16.h>
#include <cstdint>

#define NB    2
#define SEQ   4096
#define HID   512
#define NHEAD 8
#define HDIM  64
#define BM    128
#define BN    64
#define NITER (SEQ / BN)
#define L2E   1.44269504088896340736f

typedef unsigned int u32;

__device__ __forceinline__ u32 pack2h(float a, float b) {
    __half2 h = __floats2half2_rn(a, b);
    return *(u32*)&h;
}
__device__ __forceinline__ float ex2f(float x) {
    float y; asm("ex2.approx.ftz.f32 %0, %1;" : "=f"(y) : "f"(x)); return y;
}
// D += A @ B  (m16n8k16, fp16 in, fp32 acc)
__device__ __forceinline__ void mma16816(float* c, const u32* a, u32 b0, u32 b1) {
    asm volatile(
        "mma.sync.aligned.m16n8k16.row.col.f32.f16.f16.f32 "
        "{%0,%1,%2,%3}, {%4,%5,%6,%7}, {%8,%9}, {%0,%1,%2,%3};"
        : "+f"(c[0]), "+f"(c[1]), "+f"(c[2]), "+f"(c[3])
        : "r"(a[0]), "r"(a[1]), "r"(a[2]), "r"(a[3]), "r"(b0), "r"(b1));
}

__device__ float g_ctx[NB * SEQ * HID];

#define KSTR 72   // halfs per row: fragment LDS conflict-free (4n+c)

// ---------------------------------------------------------------------------
// Flash attention: QK = Q16*K16; PV = P16*V16 (fp32 acc). No-max softmax.
// Double-buffered SMEM K/V, ONE sync per tile; next tile's LDGs issued
// before/inside the MMA phases, cvt+STS spread through the softmax loop.
// ---------------------------------------------------------------------------
__global__ void __launch_bounds__(256, 2)
attn_kernel(const float* __restrict__ Q, const float* __restrict__ K,
            const float* __restrict__ V, const float* __restrict__ sigma,
            const float* __restrict__ lam_p)
{
    __shared__ __align__(16) __half sK[2][BN][KSTR];     // [stage][token][d]
    __shared__ __align__(16) __half sV[2][HDIM][KSTR];   // [stage][d][token]

    const int tid  = threadIdx.x;
    const int warp = tid >> 5;
    const int lane = tid & 31;
    const int r    = lane >> 2;
    const int c    = lane & 3;

    const int bb = blockIdx.y >> 3;
    const int hh = blockIdx.y & 7;
    const int qbase = blockIdx.x * BM;

    float sc = fminf(fmaxf(sigma[bb], 0.001f), 0.2f);
    float sn = (sc - 0.001f) * (1.0f / 0.199f);
    const float rC = lam_p[0] * 0.1f * sn * (1.0f / ((float)SEQ * (float)SEQ)) * L2E;

    const float* Qb = Q + (size_t)bb * SEQ * HID + hh * HDIM;
    const float* Kb = K + (size_t)bb * SEQ * HID + hh * HDIM;
    const float* Vb = V + (size_t)bb * SEQ * HID + hh * HDIM;

    const int k_tok  = tid >> 2;          // K staging: token row
    const int k_part = tid & 3;           // K staging: 16-d slice
    const int v_p    = tid & 31;          // V staging: token pair
    const int v_d0   = (tid >> 5) * 8;    // V staging: 8 d's

    float4 kreg[4], vreg[4];

#define LOAD_K(nb) do { \
    const float* _kr = Kb + (size_t)((nb) + k_tok) * HID + k_part * 16; \
    kreg[0] = ((const float4*)_kr)[0]; kreg[1] = ((const float4*)_kr)[1]; \
    kreg[2] = ((const float4*)_kr)[2]; kreg[3] = ((const float4*)_kr)[3]; \
} while (0)
#define LOAD_V(nb) do { \
    const float* _v0 = Vb + (size_t)((nb) + 2 * v_p) * HID + v_d0; \
    const float* _v1 = _v0 + HID; \
    vreg[0] = ((const float4*)_v0)[0]; vreg[1] = ((const float4*)_v1)[0]; \
    vreg[2] = ((const float4*)_v0)[1]; vreg[3] = ((const float4*)_v1)[1]; \
} while (0)
#define STAGE_K(buf) do { \
    _Pragma("unroll") \
    for (int _i = 0; _i < 4; _i++) { \
        float4 _v = kreg[_i]; \
        int _d = k_part * 16 + _i * 4; \
        *(u32*)&sK[buf][k_tok][_d]     = pack2h(_v.x, _v.y); \
        *(u32*)&sK[buf][k_tok][_d + 2] = pack2h(_v.z, _v.w); \
    } \
} while (0)
#define STAGE_V(buf) do { \
    _Pragma("unroll") \
    for (int _i = 0; _i < 2; _i++) { \
        float4 _a = vreg[2 * _i], _b = vreg[2 * _i + 1]; \
        float _av[4] = {_a.x, _a.y, _a.z, _a.w}; \
        float _bv[4] = {_b.x, _b.y, _b.z, _b.w}; \
        _Pragma("unroll") \
        for (int _k = 0; _k < 4; _k++) { \
            int _d = v_d0 + _i * 4 + _k; \
            *(u32*)&sV[buf][_d][2 * v_p] = pack2h(_av[_k], _bv[_k]); \
        } \
    } \
} while (0)

    // ---- Q fragments (persistent): fp16, scaled by 0.125*log2e
    u32 qf[16];
    {
        const float s = 0.125f * L2E;
        const int row0 = qbase + warp * 16 + r;
        const float* q0 = Qb + (size_t)row0 * HID;
        const float* q1 = q0 + 8 * HID;
        #pragma unroll
        for (int kc = 0; kc < 4; kc++) {
            int d = kc * 16 + 2 * c;
            qf[kc * 4 + 0] = pack2h(q0[d] * s,     q0[d + 1] * s);
            qf[kc * 4 + 1] = pack2h(q1[d] * s,     q1[d + 1] * s);
            qf[kc * 4 + 2] = pack2h(q0[d + 8] * s, q0[d + 9] * s);
            qf[kc * 4 + 3] = pack2h(q1[d + 8] * s, q1[d + 9] * s);
        }
    }

    float oacc[8][4];
    #pragma unroll
    for (int i = 0; i < 8; i++)
        #pragma unroll
        for (int j = 0; j < 4; j++) oacc[i][j] = 0.0f;
    float l0 = 0.0f, l1 = 0.0f;

    const float fi0 = (float)(qbase + warp * 16 + r);
    const float fi1 = fi0 + 8.0f;

    // ---- prologue: stage tile 0 into buffer 0
    LOAD_K(0);
    LOAD_V(0);
    STAGE_K(0);
    STAGE_V(0);
    __syncthreads();

    for (int kt = 0; kt < NITER; kt++) {
        const int kbase = kt * BN;
        const int cur = kt & 1;
        const int nxt = cur ^ 1;
        const bool has_next = (kt + 1 < NITER);

        // issue next K LDGs early — drain under QK MMAs
        if (has_next) LOAD_K(kbase + BN);

        // ---- S = Q @ K^T  (single fp16 pass)
        float sacc[8][4];
        #pragma unroll
        for (int i = 0; i < 8; i++)
            #pragma unroll
            for (int j = 0; j < 4; j++) sacc[i][j] = 0.0f;

        #pragma unroll
        for (int kc = 0; kc < 4; kc++) {
            const int kk = kc * 16 + 2 * c;
            #pragma unroll
            for (int nt = 0; nt < 8; nt++) {
                const int n = nt * 8 + r;
                u32 b0 = *(const u32*)&sK[cur][n][kk];
                u32 b1 = *(const u32*)&sK[cur][n][kk + 8];
                mma16816(sacc[nt], &qf[kc * 4], b0, b1);
            }
        }

        // issue next V LDGs — drain under softmax/PV below
        if (has_next) LOAD_V(kbase + BN);

        // ---- softmax (exp2 domain) + PV; staging STS interleaved
        #pragma unroll
        for (int kcp = 0; kcp < 4; kcp++) {
            u32 pah[4];
            #pragma unroll
            for (int half = 0; half < 2; half++) {
                const int nt = kcp * 2 + half;
                const float jb = (float)(kbase + nt * 8 + 2 * c);
                float d00 = fi0 - jb, d01 = d00 - 1.0f;
                float d10 = fi1 - jb, d11 = d10 - 1.0f;
                float p00 = ex2f(fmaf(-rC * d00, d00, sacc[nt][0]));
                float p01 = ex2f(fmaf(-rC * d01, d01, sacc[nt][1]));
                float p10 = ex2f(fmaf(-rC * d10, d10, sacc[nt][2]));
                float p11 = ex2f(fmaf(-rC * d11, d11, sacc[nt][3]));
                l0 += p00 + p01;
                l1 += p10 + p11;
                pah[half * 2 + 0] = pack2h(p00, p01);
                pah[half * 2 + 1] = pack2h(p10, p11);
            }
            const int kk = kcp * 16 + 2 * c;
            #pragma unroll
            for (int ntv = 0; ntv < 8; ntv++) {
                const int dd = ntv * 8 + r;
                u32 b0 = *(const u32*)&sV[cur][dd][kk];
                u32 b1 = *(const u32*)&sV[cur][dd][kk + 8];
                mma16816(oacc[ntv], pah, b0, b1);
            }
            if (kcp == 1 && has_next) STAGE_K(nxt);
            if (kcp == 3 && has_next) STAGE_V(nxt);
        }

        __syncthreads();   // buf[nxt] staged; buf[cur] reads complete
    }

    // ---- reduce l across the 4 lanes of each row group, normalize, store
    l0 += __shfl_xor_sync(0xffffffffu, l0, 1);
    l0 += __shfl_xor_sync(0xffffffffu, l0, 2);
    l1 += __shfl_xor_sync(0xffffffffu, l1, 1);
    l1 += __shfl_xor_sync(0xffffffffu, l1, 2);
    const float inv0 = 1.0f / l0;
    const float inv1 = 1.0f / l1;

    const int row0 = qbase + warp * 16 + r;
    float* g0 = g_ctx + ((size_t)bb * SEQ + row0) * HID + hh * HDIM + 2 * c;
    float* g1 = g0 + 8 * HID;
    #pragma unroll
    for (int ntv = 0; ntv < 8; ntv++) {
        *(float2*)(g0 + ntv * 8) = make_float2(oacc[ntv][0] * inv0, oacc[ntv][1] * inv0);
        *(float2*)(g1 + ntv * 8) = make_float2(oacc[ntv][2] * inv1, oacc[ntv][3] * inv1);
    }
}

// ---------------------------------------------------------------------------
// out = ctx @ W^T + b  (M=8192, N=512, K=512) — single-pass fp16 HMMA.
// 128x128 tile, 8 warps (4m x 2n).
// ---------------------------------------------------------------------------
#define PCH 32
#define PSTR 40

__global__ void __launch_bounds__(256, 2)
proj_kernel(const float* __restrict__ W, const float* __restrict__ bias,
            float* __restrict__ out)
{
    __shared__ __align__(16) __half sA[128][PSTR];
    __shared__ __align__(16) __half sW[128][PSTR];

    const int tid  = threadIdx.x;
    const int warp = tid >> 5;
    const int lane = tid & 31;
    const int r    = lane >> 2;
    const int c    = lane & 3;
    const int mw   = warp & 3;
    const int nw   = warp >> 2;

    const int mbase = blockIdx.x * 128;
    const int nbase = blockIdx.y * 128;

    const int r2 = tid >> 1;
    const int h2 = (tid & 1) * 16;

    float acc[2][8][4];
    #pragma unroll
    for (int mf = 0; mf < 2; mf++)
        #pragma unroll
        for (int nf = 0; nf < 8; nf++)
            #pragma unroll
            for (int j = 0; j < 4; j++) acc[mf][nf][j] = 0.0f;

    for (int kc = 0; kc < HID / PCH; kc++) {
        const int k0 = kc * PCH;
        __syncthreads();
        {
            const float* ar = g_ctx + (size_t)(mbase + r2) * HID + k0 + h2;
            #pragma unroll
            for (int i = 0; i < 4; i++) {
                float4 v = ((const float4*)ar)[i];
                *(u32*)&sA[r2][h2 + i * 4]     = pack2h(v.x, v.y);
                *(u32*)&sA[r2][h2 + i * 4 + 2] = pack2h(v.z, v.w);
            }
            const float* wr = W + (size_t)(nbase + r2) * HID + k0 + h2;
            #pragma unroll
            for (int i = 0; i < 4; i++) {
                float4 v = ((const float4*)wr)[i];
                *(u32*)&sW[r2][h2 + i * 4]     = pack2h(v.x, v.y);
                *(u32*)&sW[r2][h2 + i * 4 + 2] = pack2h(v.z, v.w);
            }
        }
        __syncthreads();

        #pragma unroll
        for (int kf = 0; kf < 2; kf++) {
            const int kk = kf * 16 + 2 * c;
            u32 ah[2][4];
            #pragma unroll
            for (int mf = 0; mf < 2; mf++) {
                const int m0 = mw * 32 + mf * 16;
                ah[mf][0] = *(const u32*)&sA[m0 + r][kk];
                ah[mf][1] = *(const u32*)&sA[m0 + r + 8][kk];
                ah[mf][2] = *(const u32*)&sA[m0 + r][kk + 8];
                ah[mf][3] = *(const u32*)&sA[m0 + r + 8][kk + 8];
            }
            #pragma unroll
            for (int nf = 0; nf < 8; nf++) {
                const int n0 = nw * 64 + nf * 8 + r;
                u32 b0 = *(const u32*)&sW[n0][kk];
                u32 b1 = *(const u32*)&sW[n0][kk + 8];
                mma16816(acc[0][nf], ah[0], b0, b1);
                mma16816(acc[1][nf], ah[1], b0, b1);
            }
        }
    }

    #pragma unroll
    for (int nf = 0; nf < 8; nf++) {
        const int n = nbase + nw * 64 + nf * 8 + 2 * c;
        const float bv0 = bias[n], bv1 = bias[n + 1];
        #pragma unroll
        for (int mf = 0; mf < 2; mf++) {
            const int m = mbase + mw * 32 + mf * 16 + r;
            *(float2*)&out[(size_t)m * HID + n] =
                make_float2(acc[mf][nf][0] + bv0, acc[mf][nf][1] + bv1);
            *(float2*)&out[(size_t)(m + 8) * HID + n] =
                make_float2(acc[mf][nf][2] + bv0, acc[mf][nf][3] + bv1);
        }
    }
}

extern "C" void kernel_launch(void* const* d_in, const int* in_sizes, int n_in,
                              void* d_out, int out_size)
{
    const float* Q     = (const float*)d_in[0];
    const float* K     = (const float*)d_in[1];
    const float* V     = (const float*)d_in[2];
    const float* sigma = (const float*)d_in[3];
    const float* lam   = (const float*)d_in[4];
    const float* W     = (const float*)d_in[5];
    const float* bias  = (const float*)d_in[6];
    float* out = (float*)d_out;

    dim3 g1(SEQ / BM, NB * NHEAD);
    attn_kernel<<<g1, 256>>>(Q, K, V, sigma, lam);

    dim3 g2(NB * SEQ / 128, HID / 128);
    proj_kernel<<<g2, 256>>>(W, bias, out);
}

// round 9
// speedup vs baseline: 6.2347x; 1.3887x over previous
#include <cuda_runtime.h>
#include <cuda_fp16.h>
#include <cstdint>

#define NB    2
#define SEQ   4096
#define HID   512
#define NHEAD 8
#define HDIM  64
#define BM    256
#define BN    64
#define NITER (SEQ / BN)
#define L2E   1.44269504088896340736f

typedef unsigned int u32;

__device__ __forceinline__ u32 pack2h(float a, float b) {
    __half2 h = __floats2half2_rn(a, b);
    return *(u32*)&h;
}
__device__ __forceinline__ float ex2f(float x) {
    float y; asm("ex2.approx.ftz.f32 %0, %1;" : "=f"(y) : "f"(x)); return y;
}
// D += A @ B  (m16n8k16, fp16 in, fp32 acc)
__device__ __forceinline__ void mma16816(float* c, const u32* a, u32 b0, u32 b1) {
    asm volatile(
        "mma.sync.aligned.m16n8k16.row.col.f32.f16.f16.f32 "
        "{%0,%1,%2,%3}, {%4,%5,%6,%7}, {%8,%9}, {%0,%1,%2,%3};"
        : "+f"(c[0]), "+f"(c[1]), "+f"(c[2]), "+f"(c[3])
        : "r"(a[0]), "r"(a[1]), "r"(a[2]), "r"(a[3]), "r"(b0), "r"(b1));
}

__device__ float g_ctx[NB * SEQ * HID];

#define KSTR 72   // halfs per row: fragment LDS conflict-free (4n+c)

// ---------------------------------------------------------------------------
// Flash attention, BM=256: warp owns 32 q-rows (2 m-frags). Each K/V
// B-fragment feeds TWO HMMAs -> B-fragment LDS bytes per q-row halved.
// QK/PV single fp16 pass, fp32 acc, no-max softmax. Double-buffered SMEM,
// one sync per tile, LDG prefetch + interleaved STS.
// ---------------------------------------------------------------------------
__global__ void __launch_bounds__(256, 1)
attn_kernel(const float* __restrict__ Q, const float* __restrict__ K,
            const float* __restrict__ V, const float* __restrict__ sigma,
            const float* __restrict__ lam_p)
{
    __shared__ __align__(16) __half sK[2][BN][KSTR];     // [stage][token][d]
    __shared__ __align__(16) __half sV[2][HDIM][KSTR];   // [stage][d][token]

    const int tid  = threadIdx.x;
    const int warp = tid >> 5;
    const int lane = tid & 31;
    const int r    = lane >> 2;
    const int c    = lane & 3;

    const int bb = blockIdx.y >> 3;
    const int hh = blockIdx.y & 7;
    const int qbase = blockIdx.x * BM;

    float sc = fminf(fmaxf(sigma[bb], 0.001f), 0.2f);
    float sn = (sc - 0.001f) * (1.0f / 0.199f);
    const float rC = lam_p[0] * 0.1f * sn * (1.0f / ((float)SEQ * (float)SEQ)) * L2E;

    const float* Qb = Q + (size_t)bb * SEQ * HID + hh * HDIM;
    const float* Kb = K + (size_t)bb * SEQ * HID + hh * HDIM;
    const float* Vb = V + (size_t)bb * SEQ * HID + hh * HDIM;

    const int k_tok  = tid >> 2;          // K staging: token row
    const int k_part = tid & 3;           // K staging: 16-d slice
    const int v_p    = tid & 31;          // V staging: token pair
    const int v_d0   = (tid >> 5) * 8;    // V staging: 8 d's

    float4 kreg[4], vreg[4];

#define LOAD_K(nb) do { \
    const float* _kr = Kb + (size_t)((nb) + k_tok) * HID + k_part * 16; \
    kreg[0] = ((const float4*)_kr)[0]; kreg[1] = ((const float4*)_kr)[1]; \
    kreg[2] = ((const float4*)_kr)[2]; kreg[3] = ((const float4*)_kr)[3]; \
} while (0)
#define LOAD_V(nb) do { \
    const float* _v0 = Vb + (size_t)((nb) + 2 * v_p) * HID + v_d0; \
    const float* _v1 = _v0 + HID; \
    vreg[0] = ((const float4*)_v0)[0]; vreg[1] = ((const float4*)_v1)[0]; \
    vreg[2] = ((const float4*)_v0)[1]; vreg[3] = ((const float4*)_v1)[1]; \
} while (0)
#define STAGE_K(buf) do { \
    _Pragma("unroll") \
    for (int _i = 0; _i < 4; _i++) { \
        float4 _v = kreg[_i]; \
        int _d = k_part * 16 + _i * 4; \
        *(u32*)&sK[buf][k_tok][_d]     = pack2h(_v.x, _v.y); \
        *(u32*)&sK[buf][k_tok][_d + 2] = pack2h(_v.z, _v.w); \
    } \
} while (0)
#define STAGE_V(buf) do { \
    _Pragma("unroll") \
    for (int _i = 0; _i < 2; _i++) { \
        float4 _a = vreg[2 * _i], _b = vreg[2 * _i + 1]; \
        float _av[4] = {_a.x, _a.y, _a.z, _a.w}; \
        float _bv[4] = {_b.x, _b.y, _b.z, _b.w}; \
        _Pragma("unroll") \
        for (int _k = 0; _k < 4; _k++) { \
            int _d = v_d0 + _i * 4 + _k; \
            *(u32*)&sV[buf][_d][2 * v_p] = pack2h(_av[_k], _bv[_k]); \
        } \
    } \
} while (0)

    // ---- Q fragments (persistent): 2 m-frags x 16 words, scaled
    u32 qf[2][16];
    {
        const float s = 0.125f * L2E;
        #pragma unroll
        for (int mf = 0; mf < 2; mf++) {
            const int row0 = qbase + warp * 32 + mf * 16 + r;
            const float* q0 = Qb + (size_t)row0 * HID;
            const float* q1 = q0 + 8 * HID;
            #pragma unroll
            for (int kc = 0; kc < 4; kc++) {
                int d = kc * 16 + 2 * c;
                qf[mf][kc * 4 + 0] = pack2h(q0[d] * s,     q0[d + 1] * s);
                qf[mf][kc * 4 + 1] = pack2h(q1[d] * s,     q1[d + 1] * s);
                qf[mf][kc * 4 + 2] = pack2h(q0[d + 8] * s, q0[d + 9] * s);
                qf[mf][kc * 4 + 3] = pack2h(q1[d + 8] * s, q1[d + 9] * s);
            }
        }
    }

    float oacc[2][8][4];
    #pragma unroll
    for (int mf = 0; mf < 2; mf++)
        #pragma unroll
        for (int i = 0; i < 8; i++)
            #pragma unroll
            for (int j = 0; j < 4; j++) oacc[mf][i][j] = 0.0f;
    float lsum[2][2] = {{0.0f, 0.0f}, {0.0f, 0.0f}};

    // ---- prologue: stage tile 0 into buffer 0
    LOAD_K(0);
    LOAD_V(0);
    STAGE_K(0);
    STAGE_V(0);
    __syncthreads();

    for (int kt = 0; kt < NITER; kt++) {
        const int kbase = kt * BN;
        const int cur = kt & 1;
        const int nxt = cur ^ 1;
        const bool has_next = (kt + 1 < NITER);

        if (has_next) LOAD_K(kbase + BN);

        // ---- S = Q @ K^T : B-frags loaded once, used for both m-frags
        float sacc[2][8][4];
        #pragma unroll
        for (int mf = 0; mf < 2; mf++)
            #pragma unroll
            for (int i = 0; i < 8; i++)
                #pragma unroll
                for (int j = 0; j < 4; j++) sacc[mf][i][j] = 0.0f;

        #pragma unroll
        for (int kc = 0; kc < 4; kc++) {
            const int kk = kc * 16 + 2 * c;
            #pragma unroll
            for (int nt = 0; nt < 8; nt++) {
                const int n = nt * 8 + r;
                u32 b0 = *(const u32*)&sK[cur][n][kk];
                u32 b1 = *(const u32*)&sK[cur][n][kk + 8];
                mma16816(sacc[0][nt], &qf[0][kc * 4], b0, b1);
                mma16816(sacc[1][nt], &qf[1][kc * 4], b0, b1);
            }
        }

        if (has_next) LOAD_V(kbase + BN);

        // ---- softmax + PV; V B-frags shared across both m-frags
        #pragma unroll
        for (int kcp = 0; kcp < 4; kcp++) {
            u32 pah[2][4];
            #pragma unroll
            for (int mf = 0; mf < 2; mf++) {
                const float fi0 = (float)(qbase + warp * 32 + mf * 16 + r);
                const float fi1 = fi0 + 8.0f;
                #pragma unroll
                for (int half = 0; half < 2; half++) {
                    const int nt = kcp * 2 + half;
                    const float jb = (float)(kbase + nt * 8 + 2 * c);
                    float d00 = fi0 - jb, d01 = d00 - 1.0f;
                    float d10 = fi1 - jb, d11 = d10 - 1.0f;
                    float p00 = ex2f(fmaf(-rC * d00, d00, sacc[mf][nt][0]));
                    float p01 = ex2f(fmaf(-rC * d01, d01, sacc[mf][nt][1]));
                    float p10 = ex2f(fmaf(-rC * d10, d10, sacc[mf][nt][2]));
                    float p11 = ex2f(fmaf(-rC * d11, d11, sacc[mf][nt][3]));
                    lsum[mf][0] += p00 + p01;
                    lsum[mf][1] += p10 + p11;
                    pah[mf][half * 2 + 0] = pack2h(p00, p01);
                    pah[mf][half * 2 + 1] = pack2h(p10, p11);
                }
            }
            const int kk = kcp * 16 + 2 * c;
            #pragma unroll
            for (int ntv = 0; ntv < 8; ntv++) {
                const int dd = ntv * 8 + r;
                u32 b0 = *(const u32*)&sV[cur][dd][kk];
                u32 b1 = *(const u32*)&sV[cur][dd][kk + 8];
                mma16816(oacc[0][ntv], pah[0], b0, b1);
                mma16816(oacc[1][ntv], pah[1], b0, b1);
            }
            if (kcp == 1 && has_next) STAGE_K(nxt);
            if (kcp == 3 && has_next) STAGE_V(nxt);
        }

        __syncthreads();   // buf[nxt] staged; buf[cur] reads complete
    }

    // ---- reduce l across the 4 lanes of each row group, normalize, store
    #pragma unroll
    for (int mf = 0; mf < 2; mf++) {
        float l0 = lsum[mf][0], l1 = lsum[mf][1];
        l0 += __shfl_xor_sync(0xffffffffu, l0, 1);
        l0 += __shfl_xor_sync(0xffffffffu, l0, 2);
        l1 += __shfl_xor_sync(0xffffffffu, l1, 1);
        l1 += __shfl_xor_sync(0xffffffffu, l1, 2);
        const float inv0 = 1.0f / l0;
        const float inv1 = 1.0f / l1;

        const int row0 = qbase + warp * 32 + mf * 16 + r;
        float* g0 = g_ctx + ((size_t)bb * SEQ + row0) * HID + hh * HDIM + 2 * c;
        float* g1 = g0 + 8 * HID;
        #pragma unroll
        for (int ntv = 0; ntv < 8; ntv++) {
            *(float2*)(g0 + ntv * 8) =
                make_float2(oacc[mf][ntv][0] * inv0, oacc[mf][ntv][1] * inv0);
            *(float2*)(g1 + ntv * 8) =
                make_float2(oacc[mf][ntv][2] * inv1, oacc[mf][ntv][3] * inv1);
        }
    }
}

// ---------------------------------------------------------------------------
// out = ctx @ W^T + b  (M=8192, N=512, K=512) — single-pass fp16 HMMA.
// 128x128 tile, 8 warps (4m x 2n).
// ---------------------------------------------------------------------------
#define PCH 32
#define PSTR 40

__global__ void __launch_bounds__(256, 2)
proj_kernel(const float* __restrict__ W, const float* __restrict__ bias,
            float* __restrict__ out)
{
    __shared__ __align__(16) __half sA[128][PSTR];
    __shared__ __align__(16) __half sW[128][PSTR];

    const int tid  = threadIdx.x;
    const int warp = tid >> 5;
    const int lane = tid & 31;
    const int r    = lane >> 2;
    const int c    = lane & 3;
    const int mw   = warp & 3;
    const int nw   = warp >> 2;

    const int mbase = blockIdx.x * 128;
    const int nbase = blockIdx.y * 128;

    const int r2 = tid >> 1;
    const int h2 = (tid & 1) * 16;

    float acc[2][8][4];
    #pragma unroll
    for (int mf = 0; mf < 2; mf++)
        #pragma unroll
        for (int nf = 0; nf < 8; nf++)
            #pragma unroll
            for (int j = 0; j < 4; j++) acc[mf][nf][j] = 0.0f;

    for (int kc = 0; kc < HID / PCH; kc++) {
        const int k0 = kc * PCH;
        __syncthreads();
        {
            const float* ar = g_ctx + (size_t)(mbase + r2) * HID + k0 + h2;
            #pragma unroll
            for (int i = 0; i < 4; i++) {
                float4 v = ((const float4*)ar)[i];
                *(u32*)&sA[r2][h2 + i * 4]     = pack2h(v.x, v.y);
                *(u32*)&sA[r2][h2 + i * 4 + 2] = pack2h(v.z, v.w);
            }
            const float* wr = W + (size_t)(nbase + r2) * HID + k0 + h2;
            #pragma unroll
            for (int i = 0; i < 4; i++) {
                float4 v = ((const float4*)wr)[i];
                *(u32*)&sW[r2][h2 + i * 4]     = pack2h(v.x, v.y);
                *(u32*)&sW[r2][h2 + i * 4 + 2] = pack2h(v.z, v.w);
            }
        }
        __syncthreads();

        #pragma unroll
        for (int kf = 0; kf < 2; kf++) {
            const int kk = kf * 16 + 2 * c;
            u32 ah[2][4];
            #pragma unroll
            for (int mf = 0; mf < 2; mf++) {
                const int m0 = mw * 32 + mf * 16;
                ah[mf][0] = *(const u32*)&sA[m0 + r][kk];
                ah[mf][1] = *(const u32*)&sA[m0 + r + 8][kk];
                ah[mf][2] = *(const u32*)&sA[m0 + r][kk + 8];
                ah[mf][3] = *(const u32*)&sA[m0 + r + 8][kk + 8];
            }
            #pragma unroll
            for (int nf = 0; nf < 8; nf++) {
                const int n0 = nw * 64 + nf * 8 + r;
                u32 b0 = *(const u32*)&sW[n0][kk];
                u32 b1 = *(const u32*)&sW[n0][kk + 8];
                mma16816(acc[0][nf], ah[0], b0, b1);
                mma16816(acc[1][nf], ah[1], b0, b1);
            }
        }
    }

    #pragma unroll
    for (int nf = 0; nf < 8; nf++) {
        const int n = nbase + nw * 64 + nf * 8 + 2 * c;
        const float bv0 = bias[n], bv1 = bias[n + 1];
        #pragma unroll
        for (int mf = 0; mf < 2; mf++) {
            const int m = mbase + mw * 32 + mf * 16 + r;
            *(float2*)&out[(size_t)m * HID + n] =
                make_float2(acc[mf][nf][0] + bv0, acc[mf][nf][1] + bv1);
            *(float2*)&out[(size_t)(m + 8) * HID + n] =
                make_float2(acc[mf][nf][2] + bv0, acc[mf][nf][3] + bv1);
        }
    }
}

extern "C" void kernel_launch(void* const* d_in, const int* in_sizes, int n_in,
                              void* d_out, int out_size)
{
    const float* Q     = (const float*)d_in[0];
    const float* K     = (const float*)d_in[1];
    const float* V     = (const float*)d_in[2];
    const float* sigma = (const float*)d_in[3];
    const float* lam   = (const float*)d_in[4];
    const float* W     = (const float*)d_in[5];
    const float* bias  = (const float*)d_in[6];
    float* out = (float*)d_out;

    dim3 g1(SEQ / BM, NB * NHEAD);
    attn_kernel<<<g1, 256>>>(Q, K, V, sigma, lam);

    dim3 g2(NB * SEQ / 128, HID / 128);
    proj_kernel<<<g2, 256>>>(W, bias, out);
}

// round 10
// speedup vs baseline: 6.4771x; 1.0389x over previous
#include <cuda_runtime.h>
#include <cuda_fp16.h>
#include <cstdint>

#define NB    2
#define SEQ   4096
#define HID   512
#define NHEAD 8
#define HDIM  64
#define BM    256
#define BN    64
#define NITER (SEQ / BN)
#define L2E   1.44269504088896340736f

typedef unsigned int u32;

// column permutation inside a 16-half chunk (8 u32 words):
// old word w -> new position (w&3)*2 | (w>>2). Puts [kk] and [kk+8]
// fragment words adjacent -> one LDS.64 per B-fragment.
#define PW(w) ((((w) & 3) << 1) | ((w) >> 2))
#define RSTR 40   // u32 words per row (80 halfs): 64-bit phases conflict-free

__device__ __forceinline__ u32 pack2h(float a, float b) {
    __half2 h = __floats2half2_rn(a, b);
    return *(u32*)&h;
}
__device__ __forceinline__ float ex2f(float x) {
    float y; asm("ex2.approx.ftz.f32 %0, %1;" : "=f"(y) : "f"(x)); return y;
}
// D += A @ B  (m16n8k16, fp16 in, fp32 acc)
__device__ __forceinline__ void mma16816(float* c, const u32* a, u32 b0, u32 b1) {
    asm volatile(
        "mma.sync.aligned.m16n8k16.row.col.f32.f16.f16.f32 "
        "{%0,%1,%2,%3}, {%4,%5,%6,%7}, {%8,%9}, {%0,%1,%2,%3};"
        : "+f"(c[0]), "+f"(c[1]), "+f"(c[2]), "+f"(c[3])
        : "r"(a[0]), "r"(a[1]), "r"(a[2]), "r"(a[3]), "r"(b0), "r"(b1));
}

__device__ float g_ctx[NB * SEQ * HID];

// ---------------------------------------------------------------------------
// Flash attention, BM=256 (warp owns 32 q-rows, 2 m-frags). Paired-fragment
// SMEM layout: every B-fragment is one LDS.64. Single-pass fp16 QK/PV,
// fp32 acc, no-max softmax, double-buffered SMEM, 1 sync/tile, LDG prefetch.
// ---------------------------------------------------------------------------
__global__ void __launch_bounds__(256, 1)
attn_kernel(const float* __restrict__ Q, const float* __restrict__ K,
            const float* __restrict__ V, const float* __restrict__ sigma,
            const float* __restrict__ lam_p)
{
    __shared__ __align__(16) u32 sK[2][BN][RSTR];     // [stage][token][chunked d]
    __shared__ __align__(16) u32 sV[2][HDIM][RSTR];   // [stage][d][chunked token]

    const int tid  = threadIdx.x;
    const int warp = tid >> 5;
    const int lane = tid & 31;
    const int r    = lane >> 2;
    const int c    = lane & 3;

    const int bb = blockIdx.y >> 3;
    const int hh = blockIdx.y & 7;
    const int qbase = blockIdx.x * BM;

    float sc = fminf(fmaxf(sigma[bb], 0.001f), 0.2f);
    float sn = (sc - 0.001f) * (1.0f / 0.199f);
    const float rC = lam_p[0] * 0.1f * sn * (1.0f / ((float)SEQ * (float)SEQ)) * L2E;

    const float* Qb = Q + (size_t)bb * SEQ * HID + hh * HDIM;
    const float* Kb = K + (size_t)bb * SEQ * HID + hh * HDIM;
    const float* Vb = V + (size_t)bb * SEQ * HID + hh * HDIM;

    const int k_tok  = tid >> 2;          // K staging: token row
    const int k_part = tid & 3;           // K staging: 16-half chunk
    const int v_p    = tid & 31;          // V staging: token pair
    const int v_d0   = (tid >> 5) * 8;    // V staging: 8 d's
    const int v_w    = (v_p >> 3) * 8 + PW(v_p & 7);  // permuted word in V row

    float4 kreg[4], vreg[4];

#define LOAD_K(nb) do { \
    const float* _kr = Kb + (size_t)((nb) + k_tok) * HID + k_part * 16; \
    kreg[0] = ((const float4*)_kr)[0]; kreg[1] = ((const float4*)_kr)[1]; \
    kreg[2] = ((const float4*)_kr)[2]; kreg[3] = ((const float4*)_kr)[3]; \
} while (0)
#define LOAD_V(nb) do { \
    const float* _v0 = Vb + (size_t)((nb) + 2 * v_p) * HID + v_d0; \
    const float* _v1 = _v0 + HID; \
    vreg[0] = ((const float4*)_v0)[0]; vreg[1] = ((const float4*)_v1)[0]; \
    vreg[2] = ((const float4*)_v0)[1]; vreg[3] = ((const float4*)_v1)[1]; \
} while (0)
// K: words 2i,2i+1 of chunk k_part -> permuted slots
#define STAGE_K(buf) do { \
    u32* _row = &sK[buf][k_tok][k_part * 8]; \
    _Pragma("unroll") \
    for (int _i = 0; _i < 4; _i++) { \
        float4 _v = kreg[_i]; \
        _row[PW(2 * _i)]     = pack2h(_v.x, _v.y); \
        _row[PW(2 * _i + 1)] = pack2h(_v.z, _v.w); \
    } \
} while (0)
#define STAGE_V(buf) do { \
    _Pragma("unroll") \
    for (int _i = 0; _i < 2; _i++) { \
        float4 _a = vreg[2 * _i], _b = vreg[2 * _i + 1]; \
        float _av[4] = {_a.x, _a.y, _a.z, _a.w}; \
        float _bv[4] = {_b.x, _b.y, _b.z, _b.w}; \
        _Pragma("unroll") \
        for (int _k = 0; _k < 4; _k++) { \
            int _d = v_d0 + _i * 4 + _k; \
            sV[buf][_d][v_w] = pack2h(_av[_k], _bv[_k]); \
        } \
    } \
} while (0)

    // ---- Q fragments (persistent): 2 m-frags x 16 words, scaled
    u32 qf[2][16];
    {
        const float s = 0.125f * L2E;
        #pragma unroll
        for (int mf = 0; mf < 2; mf++) {
            const int row0 = qbase + warp * 32 + mf * 16 + r;
            const float* q0 = Qb + (size_t)row0 * HID;
            const float* q1 = q0 + 8 * HID;
            #pragma unroll
            for (int kc = 0; kc < 4; kc++) {
                int d = kc * 16 + 2 * c;
                qf[mf][kc * 4 + 0] = pack2h(q0[d] * s,     q0[d + 1] * s);
                qf[mf][kc * 4 + 1] = pack2h(q1[d] * s,     q1[d + 1] * s);
                qf[mf][kc * 4 + 2] = pack2h(q0[d + 8] * s, q0[d + 9] * s);
                qf[mf][kc * 4 + 3] = pack2h(q1[d + 8] * s, q1[d + 9] * s);
            }
        }
    }

    float oacc[2][8][4];
    #pragma unroll
    for (int mf = 0; mf < 2; mf++)
        #pragma unroll
        for (int i = 0; i < 8; i++)
            #pragma unroll
            for (int j = 0; j < 4; j++) oacc[mf][i][j] = 0.0f;
    float lsum[2][2] = {{0.0f, 0.0f}, {0.0f, 0.0f}};

    LOAD_K(0);
    LOAD_V(0);
    STAGE_K(0);
    STAGE_V(0);
    __syncthreads();

    for (int kt = 0; kt < NITER; kt++) {
        const int kbase = kt * BN;
        const int cur = kt & 1;
        const int nxt = cur ^ 1;
        const bool has_next = (kt + 1 < NITER);

        if (has_next) LOAD_K(kbase + BN);

        // ---- S = Q @ K^T : one LDS.64 per B-frag, shared by both m-frags
        float sacc[2][8][4];
        #pragma unroll
        for (int mf = 0; mf < 2; mf++)
            #pragma unroll
            for (int i = 0; i < 8; i++)
                #pragma unroll
                for (int j = 0; j < 4; j++) sacc[mf][i][j] = 0.0f;

        #pragma unroll
        for (int kc = 0; kc < 4; kc++) {
            const int kw = kc * 8 + 2 * c;
            #pragma unroll
            for (int nt = 0; nt < 8; nt++) {
                uint2 bbv = *(const uint2*)&sK[cur][nt * 8 + r][kw];
                mma16816(sacc[0][nt], &qf[0][kc * 4], bbv.x, bbv.y);
                mma16816(sacc[1][nt], &qf[1][kc * 4], bbv.x, bbv.y);
            }
        }

        if (has_next) LOAD_V(kbase + BN);

        // ---- softmax + PV; V B-frags via LDS.64, shared across m-frags
        #pragma unroll
        for (int kcp = 0; kcp < 4; kcp++) {
            u32 pah[2][4];
            #pragma unroll
            for (int mf = 0; mf < 2; mf++) {
                const float fi0 = (float)(qbase + warp * 32 + mf * 16 + r);
                const float fi1 = fi0 + 8.0f;
                #pragma unroll
                for (int half = 0; half < 2; half++) {
                    const int nt = kcp * 2 + half;
                    const float jb = (float)(kbase + nt * 8 + 2 * c);
                    float d00 = fi0 - jb, d01 = d00 - 1.0f;
                    float d10 = fi1 - jb, d11 = d10 - 1.0f;
                    float p00 = ex2f(fmaf(-rC * d00, d00, sacc[mf][nt][0]));
                    float p01 = ex2f(fmaf(-rC * d01, d01, sacc[mf][nt][1]));
                    float p10 = ex2f(fmaf(-rC * d10, d10, sacc[mf][nt][2]));
                    float p11 = ex2f(fmaf(-rC * d11, d11, sacc[mf][nt][3]));
                    lsum[mf][0] += p00 + p01;
                    lsum[mf][1] += p10 + p11;
                    pah[mf][half * 2 + 0] = pack2h(p00, p01);
                    pah[mf][half * 2 + 1] = pack2h(p10, p11);
                }
            }
            const int kw = kcp * 8 + 2 * c;
            #pragma unroll
            for (int ntv = 0; ntv < 8; ntv++) {
                uint2 bbv = *(const uint2*)&sV[cur][ntv * 8 + r][kw];
                mma16816(oacc[0][ntv], pah[0], bbv.x, bbv.y);
                mma16816(oacc[1][ntv], pah[1], bbv.x, bbv.y);
            }
            if (kcp == 1 && has_next) STAGE_K(nxt);
            if (kcp == 3 && has_next) STAGE_V(nxt);
        }

        __syncthreads();
    }

    // ---- reduce l, normalize, store ctx
    #pragma unroll
    for (int mf = 0; mf < 2; mf++) {
        float l0 = lsum[mf][0], l1 = lsum[mf][1];
        l0 += __shfl_xor_sync(0xffffffffu, l0, 1);
        l0 += __shfl_xor_sync(0xffffffffu, l0, 2);
        l1 += __shfl_xor_sync(0xffffffffu, l1, 1);
        l1 += __shfl_xor_sync(0xffffffffu, l1, 2);
        const float inv0 = 1.0f / l0;
        const float inv1 = 1.0f / l1;

        const int row0 = qbase + warp * 32 + mf * 16 + r;
        float* g0 = g_ctx + ((size_t)bb * SEQ + row0) * HID + hh * HDIM + 2 * c;
        float* g1 = g0 + 8 * HID;
        #pragma unroll
        for (int ntv = 0; ntv < 8; ntv++) {
            *(float2*)(g0 + ntv * 8) =
                make_float2(oacc[mf][ntv][0] * inv0, oacc[mf][ntv][1] * inv0);
            *(float2*)(g1 + ntv * 8) =
                make_float2(oacc[mf][ntv][2] * inv1, oacc[mf][ntv][3] * inv1);
        }
    }
}

// ---------------------------------------------------------------------------
// out = ctx @ W^T + b  (M=8192, N=512, K=512) — fp16 HMMA, paired-fragment
// layout (LDS.64), PCH=64 (8 iters). 128x128 tile, 8 warps (4m x 2n).
// ---------------------------------------------------------------------------
#define PCH 64

__global__ void __launch_bounds__(256, 2)
proj_kernel(const float* __restrict__ W, const float* __restrict__ bias,
            float* __restrict__ out)
{
    __shared__ __align__(16) u32 sA[128][RSTR];
    __shared__ __align__(16) u32 sW[128][RSTR];

    const int tid  = threadIdx.x;
    const int warp = tid >> 5;
    const int lane = tid & 31;
    const int r    = lane >> 2;
    const int c    = lane & 3;
    const int mw   = warp & 3;
    const int nw   = warp >> 2;

    const int mbase = blockIdx.x * 128;
    const int nbase = blockIdx.y * 128;

    const int r2 = tid >> 1;              // staging row
    const int hb = (tid & 1) * 32;        // staging half-offset base
    const int cb = (tid & 1) * 2;         // staging chunk base

    float acc[2][8][4];
    #pragma unroll
    for (int mf = 0; mf < 2; mf++)
        #pragma unroll
        for (int nf = 0; nf < 8; nf++)
            #pragma unroll
            for (int j = 0; j < 4; j++) acc[mf][nf][j] = 0.0f;

    for (int kc = 0; kc < HID / PCH; kc++) {
        const int k0 = kc * PCH;
        __syncthreads();
        {
            const float* ar = g_ctx + (size_t)(mbase + r2) * HID + k0 + hb;
            const float* wr = W + (size_t)(nbase + r2) * HID + k0 + hb;
            #pragma unroll
            for (int i = 0; i < 8; i++) {
                const int ch = cb + (i >> 2);
                const int w0 = 2 * (i & 3);
                float4 a = ((const float4*)ar)[i];
                sA[r2][ch * 8 + PW(w0)]     = pack2h(a.x, a.y);
                sA[r2][ch * 8 + PW(w0 + 1)] = pack2h(a.z, a.w);
                float4 v = ((const float4*)wr)[i];
                sW[r2][ch * 8 + PW(w0)]     = pack2h(v.x, v.y);
                sW[r2][ch * 8 + PW(w0 + 1)] = pack2h(v.z, v.w);
            }
        }
        __syncthreads();

        #pragma unroll
        for (int kf = 0; kf < 4; kf++) {
            const int kw = kf * 8 + 2 * c;
            u32 ah[2][4];
            #pragma unroll
            for (int mf = 0; mf < 2; mf++) {
                const int m0 = mw * 32 + mf * 16;
                uint2 pa = *(const uint2*)&sA[m0 + r][kw];
                uint2 pb = *(const uint2*)&sA[m0 + r + 8][kw];
                ah[mf][0] = pa.x; ah[mf][1] = pb.x;
                ah[mf][2] = pa.y; ah[mf][3] = pb.y;
            }
            #pragma unroll
            for (int nf = 0; nf < 8; nf++) {
                const int n0 = nw * 64 + nf * 8 + r;
                uint2 bbv = *(const uint2*)&sW[n0][kw];
                mma16816(acc[0][nf], ah[0], bbv.x, bbv.y);
                mma16816(acc[1][nf], ah[1], bbv.x, bbv.y);
            }
        }
    }

    #pragma unroll
    for (int nf = 0; nf < 8; nf++) {
        const int n = nbase + nw * 64 + nf * 8 + 2 * c;
        const float bv0 = bias[n], bv1 = bias[n + 1];
        #pragma unroll
        for (int mf = 0; mf < 2; mf++) {
            const int m = mbase + mw * 32 + mf * 16 + r;
            *(float2*)&out[(size_t)m * HID + n] =
                make_float2(acc[mf][nf][0] + bv0, acc[mf][nf][1] + bv1);
            *(float2*)&out[(size_t)(m + 8) * HID + n] =
                make_float2(acc[mf][nf][2] + bv0, acc[mf][nf][3] + bv1);
        }
    }
}

extern "C" void kernel_launch(void* const* d_in, const int* in_sizes, int n_in,
                              void* d_out, int out_size)
{
    const float* Q     = (const float*)d_in[0];
    const float* K     = (const float*)d_in[1];
    const float* V     = (const float*)d_in[2];
    const float* sigma = (const float*)d_in[3];
    const float* lam   = (const float*)d_in[4];
    const float* W     = (const float*)d_in[5];
    const float* bias  = (const float*)d_in[6];
    float* out = (float*)d_out;

    dim3 g1(SEQ / BM, NB * NHEAD);
    attn_kernel<<<g1, 256>>>(Q, K, V, sigma, lam);

    dim3 g2(NB * SEQ / 128, HID / 128);
    proj_kernel<<<g2, 256>>>(W, bias, out);
}

// round 11
// speedup vs baseline: 6.8939x; 1.0644x over previous
#include <cuda_runtime.h>
#include <cuda_fp16.h>
#include <cstdint>

#define NB    2
#define SEQ   4096
#define HID   512
#define NHEAD 8
#define HDIM  64
#define BM    256
#define BN    64
#define NITER (SEQ / BN)
#define L2E   1.44269504088896340736f

typedef unsigned int u32;

// column permutation inside a 16-half chunk (8 u32 words):
// old word w -> new position (w&3)*2 | (w>>2). Puts [kk] and [kk+8]
// fragment words adjacent -> one LDS.64 per B-fragment.
#define PW(w) ((((w) & 3) << 1) | ((w) >> 2))
#define RSTR 40   // u32 words per row (80 halfs)

__device__ __forceinline__ u32 pack2h(float a, float b) {
    __half2 h = __floats2half2_rn(a, b);
    return *(u32*)&h;
}
__device__ __forceinline__ float ex2f(float x) {
    float y; asm("ex2.approx.ftz.f32 %0, %1;" : "=f"(y) : "f"(x)); return y;
}
// D += A @ B  (m16n8k16, fp16 in, fp32 acc)
__device__ __forceinline__ void mma16816(float* c, const u32* a, u32 b0, u32 b1) {
    asm volatile(
        "mma.sync.aligned.m16n8k16.row.col.f32.f16.f16.f32 "
        "{%0,%1,%2,%3}, {%4,%5,%6,%7}, {%8,%9}, {%0,%1,%2,%3};"
        : "+f"(c[0]), "+f"(c[1]), "+f"(c[2]), "+f"(c[3])
        : "r"(a[0]), "r"(a[1]), "r"(a[2]), "r"(a[3]), "r"(b0), "r"(b1));
}

__device__ float g_ctx[NB * SEQ * HID];

// ---------------------------------------------------------------------------
// Flash attention, BM=256, paired-fragment SMEM (LDS.64 B-frags).
// Tile processed as 4 independent {QK -> softmax -> PV} blocks so HMMA and
// MUFU phases of neighboring blocks can overlap. Single-pass fp16 QK/PV,
// fp32 acc, no-max softmax, double-buffered SMEM, 1 sync/tile.
// ---------------------------------------------------------------------------
__global__ void __launch_bounds__(256, 1)
attn_kernel(const float* __restrict__ Q, const float* __restrict__ K,
            const float* __restrict__ V, const float* __restrict__ sigma,
            const float* __restrict__ lam_p)
{
    __shared__ __align__(16) u32 sK[2][BN][RSTR];     // [stage][token][chunked d]
    __shared__ __align__(16) u32 sV[2][HDIM][RSTR];   // [stage][d][chunked token]

    const int tid  = threadIdx.x;
    const int warp = tid >> 5;
    const int lane = tid & 31;
    const int r    = lane >> 2;
    const int c    = lane & 3;

    const int bb = blockIdx.y >> 3;
    const int hh = blockIdx.y & 7;
    const int qbase = blockIdx.x * BM;

    float sc = fminf(fmaxf(sigma[bb], 0.001f), 0.2f);
    float sn = (sc - 0.001f) * (1.0f / 0.199f);
    const float rC = lam_p[0] * 0.1f * sn * (1.0f / ((float)SEQ * (float)SEQ)) * L2E;

    const float* Qb = Q + (size_t)bb * SEQ * HID + hh * HDIM;
    const float* Kb = K + (size_t)bb * SEQ * HID + hh * HDIM;
    const float* Vb = V + (size_t)bb * SEQ * HID + hh * HDIM;

    const int k_tok  = tid >> 2;
    const int k_part = tid & 3;
    const int v_p    = tid & 31;
    const int v_d0   = (tid >> 5) * 8;
    const int v_w    = (v_p >> 3) * 8 + PW(v_p & 7);

    float4 kreg[4], vreg[4];

#define LOAD_K(nb) do { \
    const float* _kr = Kb + (size_t)((nb) + k_tok) * HID + k_part * 16; \
    kreg[0] = ((const float4*)_kr)[0]; kreg[1] = ((const float4*)_kr)[1]; \
    kreg[2] = ((const float4*)_kr)[2]; kreg[3] = ((const float4*)_kr)[3]; \
} while (0)
#define LOAD_V(nb) do { \
    const float* _v0 = Vb + (size_t)((nb) + 2 * v_p) * HID + v_d0; \
    const float* _v1 = _v0 + HID; \
    vreg[0] = ((const float4*)_v0)[0]; vreg[1] = ((const float4*)_v1)[0]; \
    vreg[2] = ((const float4*)_v0)[1]; vreg[3] = ((const float4*)_v1)[1]; \
} while (0)
#define STAGE_K(buf) do { \
    u32* _row = &sK[buf][k_tok][k_part * 8]; \
    _Pragma("unroll") \
    for (int _i = 0; _i < 4; _i++) { \
        float4 _v = kreg[_i]; \
        _row[PW(2 * _i)]     = pack2h(_v.x, _v.y); \
        _row[PW(2 * _i + 1)] = pack2h(_v.z, _v.w); \
    } \
} while (0)
#define STAGE_V(buf) do { \
    _Pragma("unroll") \
    for (int _i = 0; _i < 2; _i++) { \
        float4 _a = vreg[2 * _i], _b = vreg[2 * _i + 1]; \
        float _av[4] = {_a.x, _a.y, _a.z, _a.w}; \
        float _bv[4] = {_b.x, _b.y, _b.z, _b.w}; \
        _Pragma("unroll") \
        for (int _k = 0; _k < 4; _k++) { \
            int _d = v_d0 + _i * 4 + _k; \
            sV[buf][_d][v_w] = pack2h(_av[_k], _bv[_k]); \
        } \
    } \
} while (0)

    // ---- Q fragments (persistent): 2 m-frags x 16 words, scaled
    u32 qf[2][16];
    {
        const float s = 0.125f * L2E;
        #pragma unroll
        for (int mf = 0; mf < 2; mf++) {
            const int row0 = qbase + warp * 32 + mf * 16 + r;
            const float* q0 = Qb + (size_t)row0 * HID;
            const float* q1 = q0 + 8 * HID;
            #pragma unroll
            for (int kc = 0; kc < 4; kc++) {
                int d = kc * 16 + 2 * c;
                qf[mf][kc * 4 + 0] = pack2h(q0[d] * s,     q0[d + 1] * s);
                qf[mf][kc * 4 + 1] = pack2h(q1[d] * s,     q1[d + 1] * s);
                qf[mf][kc * 4 + 2] = pack2h(q0[d + 8] * s, q0[d + 9] * s);
                qf[mf][kc * 4 + 3] = pack2h(q1[d + 8] * s, q1[d + 9] * s);
            }
        }
    }

    float oacc[2][8][4];
    #pragma unroll
    for (int mf = 0; mf < 2; mf++)
        #pragma unroll
        for (int i = 0; i < 8; i++)
            #pragma unroll
            for (int j = 0; j < 4; j++) oacc[mf][i][j] = 0.0f;
    float lsum[2][2] = {{0.0f, 0.0f}, {0.0f, 0.0f}};

    LOAD_K(0);
    LOAD_V(0);
    STAGE_K(0);
    STAGE_V(0);
    __syncthreads();

    for (int kt = 0; kt < NITER; kt++) {
        const int kbase = kt * BN;
        const int cur = kt & 1;
        const int nxt = cur ^ 1;
        const bool has_next = (kt + 1 < NITER);

        if (has_next) { LOAD_K(kbase + BN); LOAD_V(kbase + BN); }

        // ---- 4 independent blocks: QK(2 n-frags) -> softmax -> PV(chunk)
        #pragma unroll
        for (int kcp = 0; kcp < 4; kcp++) {
            // QK for n-frags 2*kcp, 2*kcp+1 (full K dim)
            float sacc[2][2][4];
            #pragma unroll
            for (int mf = 0; mf < 2; mf++)
                #pragma unroll
                for (int h = 0; h < 2; h++)
                    #pragma unroll
                    for (int j = 0; j < 4; j++) sacc[mf][h][j] = 0.0f;

            #pragma unroll
            for (int kc = 0; kc < 4; kc++) {
                const int kw = kc * 8 + 2 * c;
                #pragma unroll
                for (int h = 0; h < 2; h++) {
                    const int nt = kcp * 2 + h;
                    uint2 bbv = *(const uint2*)&sK[cur][nt * 8 + r][kw];
                    mma16816(sacc[0][h], &qf[0][kc * 4], bbv.x, bbv.y);
                    mma16816(sacc[1][h], &qf[1][kc * 4], bbv.x, bbv.y);
                }
            }

            // softmax for these 16 token columns
            u32 pah[2][4];
            #pragma unroll
            for (int mf = 0; mf < 2; mf++) {
                const float fi0 = (float)(qbase + warp * 32 + mf * 16 + r);
                const float fi1 = fi0 + 8.0f;
                #pragma unroll
                for (int h = 0; h < 2; h++) {
                    const float jb = (float)(kbase + (kcp * 2 + h) * 8 + 2 * c);
                    float d00 = fi0 - jb, d01 = d00 - 1.0f;
                    float d10 = fi1 - jb, d11 = d10 - 1.0f;
                    float p00 = ex2f(fmaf(-rC * d00, d00, sacc[mf][h][0]));
                    float p01 = ex2f(fmaf(-rC * d01, d01, sacc[mf][h][1]));
                    float p10 = ex2f(fmaf(-rC * d10, d10, sacc[mf][h][2]));
                    float p11 = ex2f(fmaf(-rC * d11, d11, sacc[mf][h][3]));
                    lsum[mf][0] += p00 + p01;
                    lsum[mf][1] += p10 + p11;
                    pah[mf][h * 2 + 0] = pack2h(p00, p01);
                    pah[mf][h * 2 + 1] = pack2h(p10, p11);
                }
            }

            // PV for this 16-token chunk
            const int kw = kcp * 8 + 2 * c;
            #pragma unroll
            for (int ntv = 0; ntv < 8; ntv++) {
                uint2 bbv = *(const uint2*)&sV[cur][ntv * 8 + r][kw];
                mma16816(oacc[0][ntv], pah[0], bbv.x, bbv.y);
                mma16816(oacc[1][ntv], pah[1], bbv.x, bbv.y);
            }

            if (kcp == 1 && has_next) STAGE_K(nxt);
            if (kcp == 3 && has_next) STAGE_V(nxt);
        }

        __syncthreads();
    }

    // ---- reduce l, normalize, store ctx
    #pragma unroll
    for (int mf = 0; mf < 2; mf++) {
        float l0 = lsum[mf][0], l1 = lsum[mf][1];
        l0 += __shfl_xor_sync(0xffffffffu, l0, 1);
        l0 += __shfl_xor_sync(0xffffffffu, l0, 2);
        l1 += __shfl_xor_sync(0xffffffffu, l1, 1);
        l1 += __shfl_xor_sync(0xffffffffu, l1, 2);
        const float inv0 = 1.0f / l0;
        const float inv1 = 1.0f / l1;

        const int row0 = qbase + warp * 32 + mf * 16 + r;
        float* g0 = g_ctx + ((size_t)bb * SEQ + row0) * HID + hh * HDIM + 2 * c;
        float* g1 = g0 + 8 * HID;
        #pragma unroll
        for (int ntv = 0; ntv < 8; ntv++) {
            *(float2*)(g0 + ntv * 8) =
                make_float2(oacc[mf][ntv][0] * inv0, oacc[mf][ntv][1] * inv0);
            *(float2*)(g1 + ntv * 8) =
                make_float2(oacc[mf][ntv][2] * inv1, oacc[mf][ntv][3] * inv1);
        }
    }
}

// ---------------------------------------------------------------------------
// out = ctx @ W^T + b  (M=8192, N=512, K=512) — single-pass fp16 HMMA.
// Round-9 proven version: 128x128 tile, PCH=32, PSTR=40 halfs, LDS.32 frags.
// ---------------------------------------------------------------------------
#define PCH 32
#define PSTR 40

__global__ void __launch_bounds__(256, 2)
proj_kernel(const float* __restrict__ W, const float* __restrict__ bias,
            float* __restrict__ out)
{
    __shared__ __align__(16) __half sA[128][PSTR];
    __shared__ __align__(16) __half sW[128][PSTR];

    const int tid  = threadIdx.x;
    const int warp = tid >> 5;
    const int lane = tid & 31;
    const int r    = lane >> 2;
    const int c    = lane & 3;
    const int mw   = warp & 3;
    const int nw   = warp >> 2;

    const int mbase = blockIdx.x * 128;
    const int nbase = blockIdx.y * 128;

    const int r2 = tid >> 1;
    const int h2 = (tid & 1) * 16;

    float acc[2][8][4];
    #pragma unroll
    for (int mf = 0; mf < 2; mf++)
        #pragma unroll
        for (int nf = 0; nf < 8; nf++)
            #pragma unroll
            for (int j = 0; j < 4; j++) acc[mf][nf][j] = 0.0f;

    for (int kc = 0; kc < HID / PCH; kc++) {
        const int k0 = kc * PCH;
        __syncthreads();
        {
            const float* ar = g_ctx + (size_t)(mbase + r2) * HID + k0 + h2;
            #pragma unroll
            for (int i = 0; i < 4; i++) {
                float4 v = ((const float4*)ar)[i];
                *(u32*)&sA[r2][h2 + i * 4]     = pack2h(v.x, v.y);
                *(u32*)&sA[r2][h2 + i * 4 + 2] = pack2h(v.z, v.w);
            }
            const float* wr = W + (size_t)(nbase + r2) * HID + k0 + h2;
            #pragma unroll
            for (int i = 0; i < 4; i++) {
                float4 v = ((const float4*)wr)[i];
                *(u32*)&sW[r2][h2 + i * 4]     = pack2h(v.x, v.y);
                *(u32*)&sW[r2][h2 + i * 4 + 2] = pack2h(v.z, v.w);
            }
        }
        __syncthreads();

        #pragma unroll
        for (int kf = 0; kf < 2; kf++) {
            const int kk = kf * 16 + 2 * c;
            u32 ah[2][4];
            #pragma unroll
            for (int mf = 0; mf < 2; mf++) {
                const int m0 = mw * 32 + mf * 16;
                ah[mf][0] = *(const u32*)&sA[m0 + r][kk];
                ah[mf][1] = *(const u32*)&sA[m0 + r + 8][kk];
                ah[mf][2] = *(const u32*)&sA[m0 + r][kk + 8];
                ah[mf][3] = *(const u32*)&sA[m0 + r + 8][kk + 8];
            }
            #pragma unroll
            for (int nf = 0; nf < 8; nf++) {
                const int n0 = nw * 64 + nf * 8 + r;
                u32 b0 = *(const u32*)&sW[n0][kk];
                u32 b1 = *(const u32*)&sW[n0][kk + 8];
                mma16816(acc[0][nf], ah[0], b0, b1);
                mma16816(acc[1][nf], ah[1], b0, b1);
            }
        }
    }

    #pragma unroll
    for (int nf = 0; nf < 8; nf++) {
        const int n = nbase + nw * 64 + nf * 8 + 2 * c;
        const float bv0 = bias[n], bv1 = bias[n + 1];
        #pragma unroll
        for (int mf = 0; mf < 2; mf++) {
            const int m = mbase + mw * 32 + mf * 16 + r;
            *(float2*)&out[(size_t)m * HID + n] =
                make_float2(acc[mf][nf][0] + bv0, acc[mf][nf][1] + bv1);
            *(float2*)&out[(size_t)(m + 8) * HID + n] =
                make_float2(acc[mf][nf][2] + bv0, acc[mf][nf][3] + bv1);
        }
    }
}

extern "C" void kernel_launch(void* const* d_in, const int* in_sizes, int n_in,
                              void* d_out, int out_size)
{
    const float* Q     = (const float*)d_in[0];
    const float* K     = (const float*)d_in[1];
    const float* V     = (const float*)d_in[2];
    const float* sigma = (const float*)d_in[3];
    const float* lam   = (const float*)d_in[4];
    const float* W     = (const float*)d_in[5];
    const float* bias  = (const float*)d_in[6];
    float* out = (float*)d_out;

    dim3 g1(SEQ / BM, NB * NHEAD);
    attn_kernel<<<g1, 256>>>(Q, K, V, sigma, lam);

    dim3 g2(NB * SEQ / 128, HID / 128);
    proj_kernel<<<g2, 256>>>(W, bias, out);
}